// round 5
// baseline (speedup 1.0000x reference)
#include <cuda_runtime.h>
#include <cuda_bf16.h>

#define EMBED   1024
#define NHEADS  16
#define DK      64
#define BATCH   8
#define SEQ     4096
#define MTOK    (BATCH * SEQ)      /* 32768 tokens */
#define BHEADS  (BATCH * NHEADS)   /* 128 head-instances */
#define NCHUNK  8
#define SCHUNK  (SEQ / NCHUNK)     /* 512 */

// ---------------------------------------------------------------------------
// Scratch: __device__ globals (the sanctioned no-alloc workaround).
//   g_QKV[0]=Q, [1]=K, [2]=V, each [MTOK][EMBED] fp32.
//   g_Gpart : per-S-chunk Gram partials  [NCHUNK][BHEADS][64][64]
//   g_At    : softmaxed attention, TRANSPOSED: g_At[bh][e][d] = attn[bh][d][e]
// ---------------------------------------------------------------------------
__device__ float g_QKV[3][MTOK * EMBED];
__device__ float g_Gpart[NCHUNK * BHEADS * DK * DK];
__device__ float g_At[BHEADS * DK * DK];

// ---------------------------------------------------------------------------
// Packed fp32x2 helpers (Blackwell sm_103a: fma.rn.f32x2 on .b64 regs)
// ---------------------------------------------------------------------------
__device__ __forceinline__ void ffma2(unsigned long long &d,
                                      unsigned long long a,
                                      unsigned long long b) {
    asm("fma.rn.f32x2 %0, %1, %2, %0;" : "+l"(d) : "l"(a), "l"(b));
}
__device__ __forceinline__ unsigned long long dup2(float x) {
    unsigned long long r;
    unsigned xi = __float_as_uint(x);
    asm("mov.b64 %0, {%1, %1};" : "=l"(r) : "r"(xi));
    return r;
}
__device__ __forceinline__ float lo2(unsigned long long v) {
    return __uint_as_float((unsigned)(v & 0xffffffffull));
}
__device__ __forceinline__ float hi2(unsigned long long v) {
    return __uint_as_float((unsigned)(v >> 32));
}

// ---------------------------------------------------------------------------
// Kernel 1: projection GEMM.  C[m][n] = sum_k X[m][k]*W[n][k] + bias[n]
// X: [MTOK][EMBED], W: [EMBED][EMBED] (row = out channel), OUT -> g_QKV[which].
// Tile 128x128x16, 256 threads, 8x8 per thread via f32x2, double-buffered smem.
// ---------------------------------------------------------------------------
#define BM  128
#define BN  128
#define BK  16
#define PADL 132   /* 132*4B = 528B row stride, 16B aligned, reduces STS conflicts */

__global__ __launch_bounds__(256, 1)
void qkv_kernel(const float* __restrict__ X, const float* __restrict__ W,
                const float* __restrict__ bias, int which)
{
    __shared__ float As[2][BK][PADL];
    __shared__ float Bs[2][BK][PADL];

    float* OUT = g_QKV[which];

    const int tid = threadIdx.x;
    const int tx  = tid & 15;          // 0..15  -> n
    const int ty  = tid >> 4;          // 0..15  -> m
    const int m0  = blockIdx.x * BM;
    const int n0  = blockIdx.y * BN;

    // global load mapping: 2 float4 from A, 2 from B per thread per k-tile
    const int lr  = tid >> 2;          // 0..63 : row within tile
    const int lc  = (tid & 3) << 2;    // 0,4,8,12 : k-col
    const float* Aptr = X + (size_t)(m0 + lr) * EMBED + lc;
    const float* Bptr = W + (size_t)(n0 + lr) * EMBED + lc;

    float4 ra0, ra1, rb0, rb1;

    // --- prime buffer 0 ---
    ra0 = *(const float4*)(Aptr);
    ra1 = *(const float4*)(Aptr + 64 * EMBED);
    rb0 = *(const float4*)(Bptr);
    rb1 = *(const float4*)(Bptr + 64 * EMBED);
    {
        const float* pa0 = (const float*)&ra0;  const float* pa1 = (const float*)&ra1;
        const float* pb0 = (const float*)&rb0;  const float* pb1 = (const float*)&rb1;
        #pragma unroll
        for (int i = 0; i < 4; i++) {
            As[0][lc + i][lr]      = pa0[i];
            As[0][lc + i][lr + 64] = pa1[i];
            Bs[0][lc + i][lr]      = pb0[i];
            Bs[0][lc + i][lr + 64] = pb1[i];
        }
    }
    __syncthreads();

    unsigned long long c2[8][4];
    #pragma unroll
    for (int i = 0; i < 8; i++)
        #pragma unroll
        for (int j = 0; j < 4; j++) c2[i][j] = 0ull;

    const int NT = EMBED / BK;   // 64 k-tiles
    for (int kt = 0; kt < NT; kt++) {
        const int cur = kt & 1;

        if (kt + 1 < NT) {   // prefetch next tile into registers
            const float* Ap = Aptr + (kt + 1) * BK;
            const float* Bp = Bptr + (kt + 1) * BK;
            ra0 = *(const float4*)(Ap);
            ra1 = *(const float4*)(Ap + 64 * EMBED);
            rb0 = *(const float4*)(Bp);
            rb1 = *(const float4*)(Bp + 64 * EMBED);
        }

        #pragma unroll
        for (int kk = 0; kk < BK; kk++) {
            float4 a0 = *(const float4*)&As[cur][kk][ty * 4];
            float4 a1 = *(const float4*)&As[cur][kk][64 + ty * 4];
            ulonglong2 b0 = *(const ulonglong2*)&Bs[cur][kk][tx * 4];
            ulonglong2 b1 = *(const ulonglong2*)&Bs[cur][kk][64 + tx * 4];
            unsigned long long bp0 = b0.x, bp1 = b0.y, bp2 = b1.x, bp3 = b1.y;
            float av[8] = {a0.x, a0.y, a0.z, a0.w, a1.x, a1.y, a1.z, a1.w};
            #pragma unroll
            for (int i = 0; i < 8; i++) {
                unsigned long long ad = dup2(av[i]);
                ffma2(c2[i][0], ad, bp0);
                ffma2(c2[i][1], ad, bp1);
                ffma2(c2[i][2], ad, bp2);
                ffma2(c2[i][3], ad, bp3);
            }
        }

        if (kt + 1 < NT) {   // store prefetched tile into the other buffer
            const int nxt = cur ^ 1;
            const float* pa0 = (const float*)&ra0;  const float* pa1 = (const float*)&ra1;
            const float* pb0 = (const float*)&rb0;  const float* pb1 = (const float*)&rb1;
            #pragma unroll
            for (int i = 0; i < 4; i++) {
                As[nxt][lc + i][lr]      = pa0[i];
                As[nxt][lc + i][lr + 64] = pa1[i];
                Bs[nxt][lc + i][lr]      = pb0[i];
                Bs[nxt][lc + i][lr + 64] = pb1[i];
            }
            __syncthreads();
        }
    }

    // --- epilogue: add bias, write ---
    const float4 biasA = *(const float4*)&bias[n0 + tx * 4];
    const float4 biasB = *(const float4*)&bias[n0 + 64 + tx * 4];
    #pragma unroll
    for (int i = 0; i < 8; i++) {
        const int m = m0 + ((i < 4) ? (ty * 4 + i) : (64 + ty * 4 + (i - 4)));
        float* orow = OUT + (size_t)m * EMBED;
        float4 v0 = make_float4(lo2(c2[i][0]) + biasA.x, hi2(c2[i][0]) + biasA.y,
                                lo2(c2[i][1]) + biasA.z, hi2(c2[i][1]) + biasA.w);
        float4 v1 = make_float4(lo2(c2[i][2]) + biasB.x, hi2(c2[i][2]) + biasB.y,
                                lo2(c2[i][3]) + biasB.z, hi2(c2[i][3]) + biasB.w);
        *(float4*)&orow[n0 + tx * 4]      = v0;
        *(float4*)&orow[n0 + 64 + tx * 4] = v1;
    }
}

// ---------------------------------------------------------------------------
// Kernel 2: Gram partials. For head-instance bh and S-chunk c:
//   Gpart[c][bh][d][e] = sum_{s in chunk} Q[b, s, h*64+d] * K[b, s, h*64+e]
// grid (128 heads, 8 chunks), 256 threads, 4x4 per thread via f32x2.
// ---------------------------------------------------------------------------
__global__ __launch_bounds__(256, 2)
void gram_kernel()
{
    __shared__ float Qs[64][64];
    __shared__ float Ks[64][64];

    const int bh    = blockIdx.x;   // 0..127
    const int chunk = blockIdx.y;   // 0..7
    const int b = bh >> 4, h = bh & 15;
    const float* Q = g_QKV[0];
    const float* K = g_QKV[1];
    const size_t base = ((size_t)b * SEQ + (size_t)chunk * SCHUNK) * EMBED + h * DK;

    const int tid = threadIdx.x;
    const int tx = tid & 15, ty = tid >> 4;
    const int lr = tid >> 4;            // 0..15 (stepped by 16 to cover 64 rows)
    const int lc4 = (tid & 15) << 2;    // 0..60

    unsigned long long c2[4][2];
    #pragma unroll
    for (int i = 0; i < 4; i++) { c2[i][0] = 0ull; c2[i][1] = 0ull; }

    for (int st = 0; st < SCHUNK / 64; st++) {   // 8 sub-tiles of 64 tokens
        #pragma unroll
        for (int rr = 0; rr < 64; rr += 16) {
            const int s = rr + lr;
            const size_t g = base + (size_t)(st * 64 + s) * EMBED + lc4;
            *(float4*)&Qs[s][lc4] = *(const float4*)(Q + g);
            *(float4*)&Ks[s][lc4] = *(const float4*)(K + g);
        }
        __syncthreads();

        #pragma unroll 8
        for (int ss = 0; ss < 64; ss++) {
            float4 q4 = *(const float4*)&Qs[ss][ty * 4];
            ulonglong2 k2 = *(const ulonglong2*)&Ks[ss][tx * 4];
            float qv[4] = {q4.x, q4.y, q4.z, q4.w};
            #pragma unroll
            for (int i = 0; i < 4; i++) {
                unsigned long long ad = dup2(qv[i]);
                ffma2(c2[i][0], ad, k2.x);
                ffma2(c2[i][1], ad, k2.y);
            }
        }
        __syncthreads();
    }

    float* gp = g_Gpart + ((size_t)chunk * BHEADS + bh) * DK * DK;
    #pragma unroll
    for (int i = 0; i < 4; i++) {
        const int d = ty * 4 + i;
        *(float4*)&gp[d * DK + tx * 4] =
            make_float4(lo2(c2[i][0]), hi2(c2[i][0]), lo2(c2[i][1]), hi2(c2[i][1]));
    }
}

// ---------------------------------------------------------------------------
// Kernel 3: reduce chunk partials + softmax over e; write attn TRANSPOSED:
//   g_At[bh][e][d] = softmax_e( 0.125 * sum_c Gpart[c][bh][d][e] )
// One warp per (bh, d) row. 8192 rows total.
// ---------------------------------------------------------------------------
__global__ __launch_bounds__(256)
void softmax_kernel()
{
    const int gwarp = (blockIdx.x * blockDim.x + threadIdx.x) >> 5;  // 0..8191
    const int lane  = threadIdx.x & 31;
    const int bh = gwarp >> 6;
    const int d  = gwarp & 63;

    float g0 = 0.f, g1 = 0.f;
    #pragma unroll
    for (int c = 0; c < NCHUNK; c++) {
        const float* gp = g_Gpart + (((size_t)c * BHEADS + bh) * DK + d) * DK;
        g0 += gp[lane];
        g1 += gp[lane + 32];
    }
    g0 *= 0.125f;   // 1/sqrt(64)
    g1 *= 0.125f;

    float m = fmaxf(g0, g1);
    #pragma unroll
    for (int o = 16; o > 0; o >>= 1) m = fmaxf(m, __shfl_xor_sync(0xffffffffu, m, o));
    float e0 = expf(g0 - m);
    float e1 = expf(g1 - m);
    float s = e0 + e1;
    #pragma unroll
    for (int o = 16; o > 0; o >>= 1) s += __shfl_xor_sync(0xffffffffu, s, o);
    const float inv = 1.0f / s;

    float* at = g_At + (size_t)bh * DK * DK;
    at[(lane)      * DK + d] = e0 * inv;
    at[(lane + 32) * DK + d] = e1 * inv;
}

// ---------------------------------------------------------------------------
// Kernel 4: output mix.  out[m, h*64+d] = sum_e attn[bh][d][e] * V[m, h*64+e]
// grid (512 token-tiles of 64, 16 heads); attn read as At[e][d] (coalesced),
// V transposed in smem. 4(s) x 4(d) per thread via f32x2 along d.
// ---------------------------------------------------------------------------
__global__ __launch_bounds__(256, 2)
void out_kernel(float* __restrict__ OUT)
{
    __shared__ float Am[64][64];     // At[e][d]
    __shared__ float Vt[64][65];     // V transposed: Vt[e][s]

    const int m0 = blockIdx.x * 64;
    const int h  = blockIdx.y;
    const int b  = m0 >> 12;         // m0 / 4096
    const int bh = b * NHEADS + h;
    const float* V = g_QKV[2];

    const int tid = threadIdx.x;
    const int tx = tid & 15, ty = tid >> 4;
    const int lr = tid >> 4;
    const int lc4 = (tid & 15) << 2;

    const float* at = g_At + (size_t)bh * DK * DK;
    #pragma unroll
    for (int rr = 0; rr < 64; rr += 16)
        *(float4*)&Am[rr + lr][lc4] = *(const float4*)&at[(rr + lr) * DK + lc4];

    #pragma unroll
    for (int rr = 0; rr < 64; rr += 16) {
        const int s = rr + lr;
        float4 v = *(const float4*)(V + (size_t)(m0 + s) * EMBED + h * DK + lc4);
        Vt[lc4 + 0][s] = v.x;
        Vt[lc4 + 1][s] = v.y;
        Vt[lc4 + 2][s] = v.z;
        Vt[lc4 + 3][s] = v.w;
    }
    __syncthreads();

    unsigned long long o2[4][2];
    #pragma unroll
    for (int i = 0; i < 4; i++) { o2[i][0] = 0ull; o2[i][1] = 0ull; }

    #pragma unroll 8
    for (int ee = 0; ee < 64; ee++) {
        ulonglong2 ap = *(const ulonglong2*)&Am[ee][tx * 4];
        #pragma unroll
        for (int si = 0; si < 4; si++) {
            unsigned long long vd = dup2(Vt[ee][ty * 4 + si]);
            ffma2(o2[si][0], vd, ap.x);
            ffma2(o2[si][1], vd, ap.y);
        }
    }

    #pragma unroll
    for (int si = 0; si < 4; si++) {
        const int m = m0 + ty * 4 + si;
        *(float4*)&OUT[(size_t)m * EMBED + h * DK + tx * 4] =
            make_float4(lo2(o2[si][0]), hi2(o2[si][0]),
                        lo2(o2[si][1]), hi2(o2[si][1]));
    }
}

// ---------------------------------------------------------------------------
// Launch: 6 kernels on the default stream, fully graph-capturable.
// ---------------------------------------------------------------------------
extern "C" void kernel_launch(void* const* d_in, const int* in_sizes, int n_in,
                              void* d_out, int out_size)
{
    const float* x  = (const float*)d_in[0];
    const float* Wq = (const float*)d_in[1];
    const float* bq = (const float*)d_in[2];
    const float* Wk = (const float*)d_in[3];
    const float* bk = (const float*)d_in[4];
    const float* Wv = (const float*)d_in[5];
    const float* bv = (const float*)d_in[6];
    float* out = (float*)d_out;

    dim3 gemm_grid(MTOK / BM, EMBED / BN);   // (256, 8)
    qkv_kernel<<<gemm_grid, 256>>>(x, Wq, bq, 0);
    qkv_kernel<<<gemm_grid, 256>>>(x, Wk, bk, 1);
    qkv_kernel<<<gemm_grid, 256>>>(x, Wv, bv, 2);

    gram_kernel<<<dim3(BHEADS, NCHUNK), 256>>>();      // (128, 8)
    softmax_kernel<<<(BHEADS * DK) / 8, 256>>>();      // 1024 blocks, warp/row
    out_kernel<<<dim3(MTOK / 64, NHEADS), 256>>>(out); // (512, 16)
}

// round 7
// speedup vs baseline: 1.8095x; 1.8095x over previous
#include <cuda_runtime.h>
#include <cuda_bf16.h>
#include <cstdint>

#define EMBED   1024
#define NHEADS  16
#define DK      64
#define BATCH   8
#define SEQ     4096
#define MTOK    (BATCH * SEQ)      /* 32768 tokens */
#define BHEADS  (BATCH * NHEADS)   /* 128 head-instances */
#define NCHUNK  8
#define SCHUNK  (SEQ / NCHUNK)     /* 512 */

// ---------------------------------------------------------------------------
// Scratch (__device__ globals: the sanctioned no-alloc workaround)
// ---------------------------------------------------------------------------
__device__ float g_QKV[3][MTOK * EMBED];                     // fp32 Q,K,V
__device__ float g_Gpart[NCHUNK * BHEADS * DK * DK];         // gram partials
__device__ float g_At[BHEADS * DK * DK];                     // attn transposed [e][d]
__device__ __nv_bfloat16 g_xh[MTOK * EMBED];                 // x hi/lo split
__device__ __nv_bfloat16 g_xl[MTOK * EMBED];
__device__ __nv_bfloat16 g_wh[3][EMBED * EMBED];             // W hi/lo split (q,k,v)
__device__ __nv_bfloat16 g_wl[3][EMBED * EMBED];

// ---------------------------------------------------------------------------
// helpers
// ---------------------------------------------------------------------------
static __device__ __forceinline__ uint32_t smem_u32(const void* p) {
    uint32_t a;
    asm("{ .reg .u64 t; cvta.to.shared.u64 t, %1; cvt.u32.u64 %0, t; }"
        : "=r"(a) : "l"(p));
    return a;
}
static __device__ __forceinline__ void cp16(uint32_t dst, const void* src) {
    asm volatile("cp.async.cg.shared.global [%0], [%1], 16;" :: "r"(dst), "l"(src));
}
#define CP_COMMIT()  asm volatile("cp.async.commit_group;" ::: "memory")
#define CP_WAIT(n)   asm volatile("cp.async.wait_group %0;" :: "n"(n) : "memory")

// mma.sync m16n8k16 row.col f32.bf16.bf16.f32 (baseline sm_80+ path)
static __device__ __forceinline__ void hmma(float* c, const uint32_t* a,
                                            uint32_t b0, uint32_t b1) {
    asm volatile(
        "mma.sync.aligned.m16n8k16.row.col.f32.bf16.bf16.f32 "
        "{%0,%1,%2,%3}, {%4,%5,%6,%7}, {%8,%9}, {%0,%1,%2,%3};"
        : "+f"(c[0]), "+f"(c[1]), "+f"(c[2]), "+f"(c[3])
        : "r"(a[0]), "r"(a[1]), "r"(a[2]), "r"(a[3]), "r"(b0), "r"(b1));
}

// packed fp32x2 helpers (for the fp32 attention kernels)
__device__ __forceinline__ void ffma2(unsigned long long &d, unsigned long long a,
                                      unsigned long long b) {
    asm("fma.rn.f32x2 %0, %1, %2, %0;" : "+l"(d) : "l"(a), "l"(b));
}
__device__ __forceinline__ unsigned long long dup2(float x) {
    unsigned long long r; unsigned xi = __float_as_uint(x);
    asm("mov.b64 %0, {%1, %1};" : "=l"(r) : "r"(xi));
    return r;
}
__device__ __forceinline__ float lo2(unsigned long long v) {
    return __uint_as_float((unsigned)(v & 0xffffffffull));
}
__device__ __forceinline__ float hi2(unsigned long long v) {
    return __uint_as_float((unsigned)(v >> 32));
}

// ---------------------------------------------------------------------------
// Kernel 0: fp32 -> bf16 hi/lo split. 4 elems per thread.
// ---------------------------------------------------------------------------
__global__ __launch_bounds__(256)
void split_kernel(const float* __restrict__ src, __nv_bfloat16* __restrict__ hi,
                  __nv_bfloat16* __restrict__ lo)
{
    const int i = (blockIdx.x * 256 + threadIdx.x) * 4;
    float4 v = *(const float4*)(src + i);
    __nv_bfloat16 h0 = __float2bfloat16(v.x);
    __nv_bfloat16 h1 = __float2bfloat16(v.y);
    __nv_bfloat16 h2 = __float2bfloat16(v.z);
    __nv_bfloat16 h3 = __float2bfloat16(v.w);
    __nv_bfloat16 l0 = __float2bfloat16(v.x - __bfloat162float(h0));
    __nv_bfloat16 l1 = __float2bfloat16(v.y - __bfloat162float(h1));
    __nv_bfloat16 l2 = __float2bfloat16(v.z - __bfloat162float(h2));
    __nv_bfloat16 l3 = __float2bfloat16(v.w - __bfloat162float(h3));
    __nv_bfloat162 hp0 = {h0, h1}, hp1 = {h2, h3};
    __nv_bfloat162 lp0 = {l0, l1}, lp1 = {l2, l3};
    *(__nv_bfloat162*)(hi + i)     = hp0;
    *(__nv_bfloat162*)(hi + i + 2) = hp1;
    *(__nv_bfloat162*)(lo + i)     = lp0;
    *(__nv_bfloat162*)(lo + i + 2) = lp1;
}

// ---------------------------------------------------------------------------
// Kernel 1: mma.sync projection GEMM with bf16 hi/lo split.
//   C[m][n] = sum_k X[m][k]*W[n][k] + bias[n]
//   = Xh*Wh + Xh*Wl + Xl*Wh   (fp32 register accumulators)
// CTA tile 128x128, 256 threads (8 warps: 4M x 2N, warp tile 32x64).
// K streamed in 32-wide chunks; double-buffered cp.async stages.
// SMEM rows padded to 40 bf16 (20 words): LDS bank-conflict-free.
// ---------------------------------------------------------------------------
#define GBK        32
#define G_NCH      (EMBED / GBK)        /* 32 chunks */
#define PADW       40                   /* bf16 per padded row */
#define MAT_BYTES  (128 * PADW * 2)     /* 10240 */
#define STAGE_B    (4 * MAT_BYTES)      /* 40960 */
#define G_SMEM     (2 * STAGE_B)        /* 81920 */

static __device__ __forceinline__ void load_chunk(
    uint32_t sb, int buf, int c, int m0, int n0,
    const __nv_bfloat16* __restrict__ Ah, const __nv_bfloat16* __restrict__ Al,
    const __nv_bfloat16* __restrict__ Bh, const __nv_bfloat16* __restrict__ Bl,
    int tid)
{
    const uint32_t st = sb + buf * STAGE_B;
    #pragma unroll
    for (int i = 0; i < 2; i++) {
        const int slot = i * 256 + tid;          // 0..511
        const int row = slot >> 2;               // 0..127
        const int seg = slot & 3;                // 16B segment (8 bf16)
        const uint32_t d = row * (PADW * 2) + seg * 16;
        const size_t gA = (size_t)(m0 + row) * EMBED + c * GBK + seg * 8;
        const size_t gB = (size_t)(n0 + row) * EMBED + c * GBK + seg * 8;
        cp16(st + 0 * MAT_BYTES + d, Ah + gA);
        cp16(st + 1 * MAT_BYTES + d, Al + gA);
        cp16(st + 2 * MAT_BYTES + d, Bh + gB);
        cp16(st + 3 * MAT_BYTES + d, Bl + gB);
    }
    CP_COMMIT();
}

__global__ __launch_bounds__(256, 2)
void gemm_split_kernel(const __nv_bfloat16* __restrict__ Ah,
                       const __nv_bfloat16* __restrict__ Al,
                       const __nv_bfloat16* __restrict__ Bh,
                       const __nv_bfloat16* __restrict__ Bl,
                       const float* __restrict__ bias,
                       float* __restrict__ C)
{
    extern __shared__ char smem[];
    const uint32_t sb = smem_u32(smem);
    const int tid  = threadIdx.x;
    const int wid  = tid >> 5;
    const int lane = tid & 31;
    const int g    = lane >> 2;          // group id 0..7
    const int tg   = lane & 3;           // thread in group 0..3

    const int n0 = blockIdx.x * 128;     // x fastest: CTAs sharing m0 reuse A in L2
    const int m0 = blockIdx.y * 128;

    const int wm = wid & 3;              // 0..3 -> M offset
    const int wn = wid >> 2;             // 0..1 -> N offset

    float acc[2][8][4];
    #pragma unroll
    for (int mt = 0; mt < 2; mt++)
        #pragma unroll
        for (int nt = 0; nt < 8; nt++)
            #pragma unroll
            for (int r = 0; r < 4; r++) acc[mt][nt][r] = 0.f;

    load_chunk(sb, 0, 0, m0, n0, Ah, Al, Bh, Bl, tid);

    for (int c = 0; c < G_NCH; c++) {
        const int buf = c & 1;
        if (c + 1 < G_NCH) {
            load_chunk(sb, buf ^ 1, c + 1, m0, n0, Ah, Al, Bh, Bl, tid);
            CP_WAIT(1);
        } else {
            CP_WAIT(0);
        }
        __syncthreads();

        const char* st = smem + buf * STAGE_B;
        const __nv_bfloat16* sAh = (const __nv_bfloat16*)(st);
        const __nv_bfloat16* sAl = (const __nv_bfloat16*)(st + MAT_BYTES);
        const __nv_bfloat16* sBh = (const __nv_bfloat16*)(st + 2 * MAT_BYTES);
        const __nv_bfloat16* sBl = (const __nv_bfloat16*)(st + 3 * MAT_BYTES);

        #pragma unroll
        for (int step = 0; step < 2; step++) {
            const int kb = step * 16;

            uint32_t ah[2][4], al[2][4];
            #pragma unroll
            for (int mt = 0; mt < 2; mt++) {
                const int r0 = wm * 32 + mt * 16 + g;
                const int o0 = r0 * PADW + kb + 2 * tg;
                const int o1 = (r0 + 8) * PADW + kb + 2 * tg;
                ah[mt][0] = *(const uint32_t*)&sAh[o0];
                ah[mt][1] = *(const uint32_t*)&sAh[o1];
                ah[mt][2] = *(const uint32_t*)&sAh[o0 + 8];
                ah[mt][3] = *(const uint32_t*)&sAh[o1 + 8];
                al[mt][0] = *(const uint32_t*)&sAl[o0];
                al[mt][1] = *(const uint32_t*)&sAl[o1];
                al[mt][2] = *(const uint32_t*)&sAl[o0 + 8];
                al[mt][3] = *(const uint32_t*)&sAl[o1 + 8];
            }

            #pragma unroll
            for (int nt = 0; nt < 8; nt++) {
                const int nr = wn * 64 + nt * 8 + g;
                const int ob = nr * PADW + kb + 2 * tg;
                const uint32_t bh0 = *(const uint32_t*)&sBh[ob];
                const uint32_t bh1 = *(const uint32_t*)&sBh[ob + 8];
                const uint32_t bl0 = *(const uint32_t*)&sBl[ob];
                const uint32_t bl1 = *(const uint32_t*)&sBl[ob + 8];
                #pragma unroll
                for (int mt = 0; mt < 2; mt++) {
                    hmma(acc[mt][nt], ah[mt], bh0, bh1);   // hi*hi
                    hmma(acc[mt][nt], ah[mt], bl0, bl1);   // hi*lo
                    hmma(acc[mt][nt], al[mt], bh0, bh1);   // lo*hi
                }
            }
        }
        __syncthreads();
    }

    // epilogue: c0,c1 -> (row g, cols 2tg,2tg+1); c2,c3 -> row g+8
    #pragma unroll
    for (int mt = 0; mt < 2; mt++) {
        const int row = m0 + wm * 32 + mt * 16 + g;
        #pragma unroll
        for (int nt = 0; nt < 8; nt++) {
            const int col = n0 + wn * 64 + nt * 8 + 2 * tg;
            const float2 bv = *(const float2*)&bias[col];
            float2 v0 = make_float2(acc[mt][nt][0] + bv.x, acc[mt][nt][1] + bv.y);
            float2 v1 = make_float2(acc[mt][nt][2] + bv.x, acc[mt][nt][3] + bv.y);
            *(float2*)&C[(size_t)row * EMBED + col]       = v0;
            *(float2*)&C[(size_t)(row + 8) * EMBED + col] = v1;
        }
    }
}

// ---------------------------------------------------------------------------
// Kernel 2: Gram partials (fp32, f32x2). Gpart[c][bh][d][e] = sum_s Q.K
// ---------------------------------------------------------------------------
__global__ __launch_bounds__(256, 2)
void gram_kernel()
{
    __shared__ float Qs[64][64];
    __shared__ float Ks[64][64];

    const int bh = blockIdx.x, chunk = blockIdx.y;
    const int b = bh >> 4, h = bh & 15;
    const float* Q = g_QKV[0];
    const float* K = g_QKV[1];
    const size_t base = ((size_t)b * SEQ + (size_t)chunk * SCHUNK) * EMBED + h * DK;

    const int tid = threadIdx.x;
    const int tx = tid & 15, ty = tid >> 4;
    const int lr = tid >> 4, lc4 = (tid & 15) << 2;

    unsigned long long c2[4][2];
    #pragma unroll
    for (int i = 0; i < 4; i++) { c2[i][0] = 0ull; c2[i][1] = 0ull; }

    for (int st = 0; st < SCHUNK / 64; st++) {
        #pragma unroll
        for (int rr = 0; rr < 64; rr += 16) {
            const int s = rr + lr;
            const size_t gg = base + (size_t)(st * 64 + s) * EMBED + lc4;
            *(float4*)&Qs[s][lc4] = *(const float4*)(Q + gg);
            *(float4*)&Ks[s][lc4] = *(const float4*)(K + gg);
        }
        __syncthreads();

        #pragma unroll 8
        for (int ss = 0; ss < 64; ss++) {
            float4 q4 = *(const float4*)&Qs[ss][ty * 4];
            ulonglong2 k2 = *(const ulonglong2*)&Ks[ss][tx * 4];
            float qv[4] = {q4.x, q4.y, q4.z, q4.w};
            #pragma unroll
            for (int i = 0; i < 4; i++) {
                unsigned long long ad = dup2(qv[i]);
                ffma2(c2[i][0], ad, k2.x);
                ffma2(c2[i][1], ad, k2.y);
            }
        }
        __syncthreads();
    }

    float* gp = g_Gpart + ((size_t)chunk * BHEADS + bh) * DK * DK;
    #pragma unroll
    for (int i = 0; i < 4; i++) {
        const int d = ty * 4 + i;
        *(float4*)&gp[d * DK + tx * 4] =
            make_float4(lo2(c2[i][0]), hi2(c2[i][0]), lo2(c2[i][1]), hi2(c2[i][1]));
    }
}

// ---------------------------------------------------------------------------
// Kernel 3: reduce partials + softmax; write attn transposed At[e][d]
// ---------------------------------------------------------------------------
__global__ __launch_bounds__(256)
void softmax_kernel()
{
    const int gwarp = (blockIdx.x * blockDim.x + threadIdx.x) >> 5;
    const int lane = threadIdx.x & 31;
    const int bh = gwarp >> 6;
    const int d = gwarp & 63;

    float g0 = 0.f, g1 = 0.f;
    #pragma unroll
    for (int c = 0; c < NCHUNK; c++) {
        const float* gp = g_Gpart + (((size_t)c * BHEADS + bh) * DK + d) * DK;
        g0 += gp[lane];
        g1 += gp[lane + 32];
    }
    g0 *= 0.125f; g1 *= 0.125f;

    float m = fmaxf(g0, g1);
    #pragma unroll
    for (int o = 16; o > 0; o >>= 1) m = fmaxf(m, __shfl_xor_sync(0xffffffffu, m, o));
    float e0 = expf(g0 - m), e1 = expf(g1 - m);
    float s = e0 + e1;
    #pragma unroll
    for (int o = 16; o > 0; o >>= 1) s += __shfl_xor_sync(0xffffffffu, s, o);
    const float inv = 1.0f / s;

    float* at = g_At + (size_t)bh * DK * DK;
    at[lane * DK + d]        = e0 * inv;
    at[(lane + 32) * DK + d] = e1 * inv;
}

// ---------------------------------------------------------------------------
// Kernel 4: output mix  out[m, h*64+d] = sum_e attn[bh][d][e] * V[m, h*64+e]
// ---------------------------------------------------------------------------
__global__ __launch_bounds__(256, 2)
void out_kernel(float* __restrict__ OUT)
{
    __shared__ float Am[64][64];
    __shared__ float Vt[64][65];

    const int m0 = blockIdx.x * 64;
    const int h  = blockIdx.y;
    const int b  = m0 >> 12;
    const int bh = b * NHEADS + h;
    const float* V = g_QKV[2];

    const int tid = threadIdx.x;
    const int tx = tid & 15, ty = tid >> 4;
    const int lr = tid >> 4, lc4 = (tid & 15) << 2;

    const float* at = g_At + (size_t)bh * DK * DK;
    #pragma unroll
    for (int rr = 0; rr < 64; rr += 16)
        *(float4*)&Am[rr + lr][lc4] = *(const float4*)&at[(rr + lr) * DK + lc4];

    #pragma unroll
    for (int rr = 0; rr < 64; rr += 16) {
        const int s = rr + lr;
        float4 v = *(const float4*)(V + (size_t)(m0 + s) * EMBED + h * DK + lc4);
        Vt[lc4 + 0][s] = v.x;
        Vt[lc4 + 1][s] = v.y;
        Vt[lc4 + 2][s] = v.z;
        Vt[lc4 + 3][s] = v.w;
    }
    __syncthreads();

    unsigned long long o2[4][2];
    #pragma unroll
    for (int i = 0; i < 4; i++) { o2[i][0] = 0ull; o2[i][1] = 0ull; }

    #pragma unroll 8
    for (int ee = 0; ee < 64; ee++) {
        ulonglong2 ap = *(const ulonglong2*)&Am[ee][tx * 4];
        #pragma unroll
        for (int si = 0; si < 4; si++) {
            unsigned long long vd = dup2(Vt[ee][ty * 4 + si]);
            ffma2(o2[si][0], vd, ap.x);
            ffma2(o2[si][1], vd, ap.y);
        }
    }

    #pragma unroll
    for (int si = 0; si < 4; si++) {
        const int m = m0 + ty * 4 + si;
        *(float4*)&OUT[(size_t)m * EMBED + h * DK + tx * 4] =
            make_float4(lo2(o2[si][0]), hi2(o2[si][0]),
                        lo2(o2[si][1]), hi2(o2[si][1]));
    }
}

// ---------------------------------------------------------------------------
// Launch
// ---------------------------------------------------------------------------
extern "C" void kernel_launch(void* const* d_in, const int* in_sizes, int n_in,
                              void* d_out, int out_size)
{
    const float* x  = (const float*)d_in[0];
    const float* Wq = (const float*)d_in[1];
    const float* bq = (const float*)d_in[2];
    const float* Wk = (const float*)d_in[3];
    const float* bk = (const float*)d_in[4];
    const float* Wv = (const float*)d_in[5];
    const float* bv = (const float*)d_in[6];
    float* out = (float*)d_out;

    cudaFuncSetAttribute(gemm_split_kernel,
                         cudaFuncAttributeMaxDynamicSharedMemorySize, G_SMEM);

    __nv_bfloat16 *xh, *xl, *whb, *wlb;
    cudaGetSymbolAddress((void**)&xh,  g_xh);
    cudaGetSymbolAddress((void**)&xl,  g_xl);
    cudaGetSymbolAddress((void**)&whb, g_wh);
    cudaGetSymbolAddress((void**)&wlb, g_wl);
    float* qkv;
    cudaGetSymbolAddress((void**)&qkv, g_QKV);

    __nv_bfloat16* wh[3] = {whb, whb + EMBED * EMBED, whb + 2 * EMBED * EMBED};
    __nv_bfloat16* wl[3] = {wlb, wlb + EMBED * EMBED, wlb + 2 * EMBED * EMBED};

    // 1) hi/lo splits
    split_kernel<<<(MTOK * EMBED) / 1024, 256>>>(x, xh, xl);
    split_kernel<<<(EMBED * EMBED) / 1024, 256>>>(Wq, wh[0], wl[0]);
    split_kernel<<<(EMBED * EMBED) / 1024, 256>>>(Wk, wh[1], wl[1]);
    split_kernel<<<(EMBED * EMBED) / 1024, 256>>>(Wv, wh[2], wl[2]);

    // 2) tensor-core projections (mma.sync path; N fastest for L2 A reuse)
    dim3 ggrid(EMBED / 128, MTOK / 128);   // (8, 256)
    gemm_split_kernel<<<ggrid, 256, G_SMEM>>>(xh, xl, wh[0], wl[0], bq,
                                              qkv + 0ll * MTOK * EMBED);
    gemm_split_kernel<<<ggrid, 256, G_SMEM>>>(xh, xl, wh[1], wl[1], bk,
                                              qkv + 1ll * MTOK * EMBED);
    gemm_split_kernel<<<ggrid, 256, G_SMEM>>>(xh, xl, wh[2], wl[2], bv,
                                              qkv + 2ll * MTOK * EMBED);

    // 3) attention over channels
    gram_kernel<<<dim3(BHEADS, NCHUNK), 256>>>();
    softmax_kernel<<<(BHEADS * DK) / 8, 256>>>();
    out_kernel<<<dim3(MTOK / 64, NHEADS), 256>>>(out);
}

// round 8
// speedup vs baseline: 1.9309x; 1.0671x over previous
#include <cuda_runtime.h>
#include <cuda_bf16.h>
#include <cstdint>

#define EMBED   1024
#define NHEADS  16
#define DK      64
#define BATCH   8
#define SEQ     4096
#define MTOK    (BATCH * SEQ)      /* 32768 tokens */
#define BHEADS  (BATCH * NHEADS)   /* 128 head-instances */
#define NCHUNK  8
#define SCHUNK  (SEQ / NCHUNK)     /* 512 */

// ---------------------------------------------------------------------------
// Scratch (__device__ globals: the sanctioned no-alloc workaround)
// ---------------------------------------------------------------------------
__device__ float g_QKV[3][MTOK * EMBED];                     // fp32 Q,K,V
__device__ float g_Gpart[NCHUNK * BHEADS * DK * DK];         // gram partials
__device__ float g_At[BHEADS * DK * DK];                     // attn transposed [e][d]
__device__ __nv_bfloat16 g_xh[MTOK * EMBED];                 // x hi/lo split
__device__ __nv_bfloat16 g_xl[MTOK * EMBED];
__device__ __nv_bfloat16 g_wh[3][EMBED * EMBED];             // W hi/lo split (q,k,v)
__device__ __nv_bfloat16 g_wl[3][EMBED * EMBED];

// ---------------------------------------------------------------------------
// helpers
// ---------------------------------------------------------------------------
static __device__ __forceinline__ uint32_t smem_u32(const void* p) {
    uint32_t a;
    asm("{ .reg .u64 t; cvta.to.shared.u64 t, %1; cvt.u32.u64 %0, t; }"
        : "=r"(a) : "l"(p));
    return a;
}
static __device__ __forceinline__ void cp16(uint32_t dst, const void* src) {
    asm volatile("cp.async.cg.shared.global [%0], [%1], 16;" :: "r"(dst), "l"(src));
}
#define CP_COMMIT()  asm volatile("cp.async.commit_group;" ::: "memory")
#define CP_WAIT(n)   asm volatile("cp.async.wait_group %0;" :: "n"(n) : "memory")

// mma.sync m16n8k16 row.col f32.bf16.bf16.f32 (baseline sm_80+ path)
static __device__ __forceinline__ void hmma(float* c, const uint32_t* a,
                                            uint32_t b0, uint32_t b1) {
    asm volatile(
        "mma.sync.aligned.m16n8k16.row.col.f32.bf16.bf16.f32 "
        "{%0,%1,%2,%3}, {%4,%5,%6,%7}, {%8,%9}, {%0,%1,%2,%3};"
        : "+f"(c[0]), "+f"(c[1]), "+f"(c[2]), "+f"(c[3])
        : "r"(a[0]), "r"(a[1]), "r"(a[2]), "r"(a[3]), "r"(b0), "r"(b1));
}
// ldmatrix x4: fills 4 fragment regs from 4 8x8 b16 tiles (lane-group addressed)
static __device__ __forceinline__ void ldsm4(uint32_t* r, uint32_t addr) {
    asm volatile("ldmatrix.sync.aligned.m8n8.x4.shared.b16 {%0,%1,%2,%3}, [%4];"
                 : "=r"(r[0]), "=r"(r[1]), "=r"(r[2]), "=r"(r[3]) : "r"(addr));
}

// packed fp32x2 helpers (for the fp32 attention kernels)
__device__ __forceinline__ void ffma2(unsigned long long &d, unsigned long long a,
                                      unsigned long long b) {
    asm("fma.rn.f32x2 %0, %1, %2, %0;" : "+l"(d) : "l"(a), "l"(b));
}
__device__ __forceinline__ unsigned long long dup2(float x) {
    unsigned long long r; unsigned xi = __float_as_uint(x);
    asm("mov.b64 %0, {%1, %1};" : "=l"(r) : "r"(xi));
    return r;
}
__device__ __forceinline__ float lo2(unsigned long long v) {
    return __uint_as_float((unsigned)(v & 0xffffffffull));
}
__device__ __forceinline__ float hi2(unsigned long long v) {
    return __uint_as_float((unsigned)(v >> 32));
}

// ---------------------------------------------------------------------------
// Kernel 0: fp32 -> bf16 hi/lo split. 4 elems per thread.
// ---------------------------------------------------------------------------
__global__ __launch_bounds__(256)
void split_kernel(const float* __restrict__ src, __nv_bfloat16* __restrict__ hi,
                  __nv_bfloat16* __restrict__ lo)
{
    const int i = (blockIdx.x * 256 + threadIdx.x) * 4;
    float4 v = *(const float4*)(src + i);
    __nv_bfloat16 h0 = __float2bfloat16(v.x);
    __nv_bfloat16 h1 = __float2bfloat16(v.y);
    __nv_bfloat16 h2 = __float2bfloat16(v.z);
    __nv_bfloat16 h3 = __float2bfloat16(v.w);
    __nv_bfloat16 l0 = __float2bfloat16(v.x - __bfloat162float(h0));
    __nv_bfloat16 l1 = __float2bfloat16(v.y - __bfloat162float(h1));
    __nv_bfloat16 l2 = __float2bfloat16(v.z - __bfloat162float(h2));
    __nv_bfloat16 l3 = __float2bfloat16(v.w - __bfloat162float(h3));
    __nv_bfloat162 hp0 = {h0, h1}, hp1 = {h2, h3};
    __nv_bfloat162 lp0 = {l0, l1}, lp1 = {l2, l3};
    *(__nv_bfloat162*)(hi + i)     = hp0;
    *(__nv_bfloat162*)(hi + i + 2) = hp1;
    *(__nv_bfloat162*)(lo + i)     = lp0;
    *(__nv_bfloat162*)(lo + i + 2) = lp1;
}

// ---------------------------------------------------------------------------
// Kernel 1: mma.sync projection GEMM with bf16 hi/lo split + ldmatrix frags.
//   C[m][n] = sum_k X[m][k]*W[n][k] + bias[n]
//   = Xh*Wh + Xh*Wl + Xl*Wh   (fp32 register accumulators)
// CTA tile 128x128, 256 threads (8 warps: 4M x 2N, warp tile 32x64).
// K streamed in 32-wide chunks; double-buffered cp.async stages.
// SMEM rows padded to 40 bf16 (80 B): ldmatrix 8-row phases hit all 32 banks.
// ---------------------------------------------------------------------------
#define GBK        32
#define G_NCH      (EMBED / GBK)        /* 32 chunks */
#define PADW       40                   /* bf16 per padded row */
#define ROWB       (PADW * 2)           /* 80 bytes per row */
#define MAT_BYTES  (128 * ROWB)         /* 10240 */
#define STAGE_B    (4 * MAT_BYTES)      /* 40960 */
#define G_SMEM     (2 * STAGE_B)        /* 81920 */

static __device__ __forceinline__ void load_chunk(
    uint32_t sb, int buf, int c, int m0, int n0,
    const __nv_bfloat16* __restrict__ Ah, const __nv_bfloat16* __restrict__ Al,
    const __nv_bfloat16* __restrict__ Bh, const __nv_bfloat16* __restrict__ Bl,
    int tid)
{
    const uint32_t st = sb + buf * STAGE_B;
    #pragma unroll
    for (int i = 0; i < 2; i++) {
        const int slot = i * 256 + tid;          // 0..511
        const int row = slot >> 2;               // 0..127
        const int seg = slot & 3;                // 16B segment (8 bf16)
        const uint32_t d = row * ROWB + seg * 16;
        const size_t gA = (size_t)(m0 + row) * EMBED + c * GBK + seg * 8;
        const size_t gB = (size_t)(n0 + row) * EMBED + c * GBK + seg * 8;
        cp16(st + 0 * MAT_BYTES + d, Ah + gA);
        cp16(st + 1 * MAT_BYTES + d, Al + gA);
        cp16(st + 2 * MAT_BYTES + d, Bh + gB);
        cp16(st + 3 * MAT_BYTES + d, Bl + gB);
    }
    CP_COMMIT();
}

__global__ __launch_bounds__(256, 2)
void gemm_split_kernel(const __nv_bfloat16* __restrict__ Ah,
                       const __nv_bfloat16* __restrict__ Al,
                       const __nv_bfloat16* __restrict__ Bh,
                       const __nv_bfloat16* __restrict__ Bl,
                       const float* __restrict__ bias,
                       float* __restrict__ C)
{
    extern __shared__ char smem[];
    const uint32_t sb = smem_u32(smem);
    const int tid  = threadIdx.x;
    const int wid  = tid >> 5;
    const int lane = tid & 31;
    const int g    = lane >> 2;          // row group 0..7 (c-fragment row)
    const int tg   = lane & 3;           // col pair 0..3

    const int n0 = blockIdx.x * 128;     // x fastest: CTAs sharing m0 reuse A in L2
    const int m0 = blockIdx.y * 128;

    const int wm = wid & 3;              // 0..3 -> M offset
    const int wn = wid >> 2;             // 0..1 -> N offset

    // ldmatrix per-lane base byte offsets.
    // A x4 group map: g0: rows0-7@k0, g1: rows8-15@k0, g2: rows0-7@k8, g3: rows8-15@k8
    // B x4 group map: g0: n0-7@k0,    g1: n0-7@k8,    g2: n8-15@k0,   g3: n8-15@k8
    const int grp = lane >> 3, lr8 = lane & 7;
    const uint32_t aoff = (uint32_t)((wm * 32 + (grp & 1) * 8 + lr8) * ROWB
                                     + (grp >> 1) * 16);
    const uint32_t boff = (uint32_t)((wn * 64 + (grp >> 1) * 8 + lr8) * ROWB
                                     + (grp & 1) * 16);

    float acc[2][8][4];
    #pragma unroll
    for (int mt = 0; mt < 2; mt++)
        #pragma unroll
        for (int nt = 0; nt < 8; nt++)
            #pragma unroll
            for (int r = 0; r < 4; r++) acc[mt][nt][r] = 0.f;

    load_chunk(sb, 0, 0, m0, n0, Ah, Al, Bh, Bl, tid);

    for (int c = 0; c < G_NCH; c++) {
        const int buf = c & 1;
        if (c + 1 < G_NCH) {
            load_chunk(sb, buf ^ 1, c + 1, m0, n0, Ah, Al, Bh, Bl, tid);
            CP_WAIT(1);
        } else {
            CP_WAIT(0);
        }
        __syncthreads();

        const uint32_t stAh = sb + buf * STAGE_B;
        const uint32_t stAl = stAh + MAT_BYTES;
        const uint32_t stBh = stAh + 2 * MAT_BYTES;
        const uint32_t stBl = stAh + 3 * MAT_BYTES;

        #pragma unroll
        for (int step = 0; step < 2; step++) {
            const uint32_t so = step * 32;       // 16 bf16 = 32 B along k

            uint32_t ah[2][4], al[2][4];
            #pragma unroll
            for (int mt = 0; mt < 2; mt++) {
                ldsm4(ah[mt], stAh + aoff + mt * (16 * ROWB) + so);
                ldsm4(al[mt], stAl + aoff + mt * (16 * ROWB) + so);
            }

            #pragma unroll
            for (int pr = 0; pr < 4; pr++) {     // n-row pairs: 2 n8 tiles each
                uint32_t bh4[4], bl4[4];
                ldsm4(bh4, stBh + boff + pr * (16 * ROWB) + so);
                ldsm4(bl4, stBl + boff + pr * (16 * ROWB) + so);
                #pragma unroll
                for (int mt = 0; mt < 2; mt++) {
                    hmma(acc[mt][2 * pr],     ah[mt], bh4[0], bh4[1]);  // hi*hi
                    hmma(acc[mt][2 * pr],     ah[mt], bl4[0], bl4[1]);  // hi*lo
                    hmma(acc[mt][2 * pr],     al[mt], bh4[0], bh4[1]);  // lo*hi
                    hmma(acc[mt][2 * pr + 1], ah[mt], bh4[2], bh4[3]);
                    hmma(acc[mt][2 * pr + 1], ah[mt], bl4[2], bl4[3]);
                    hmma(acc[mt][2 * pr + 1], al[mt], bh4[2], bh4[3]);
                }
            }
        }
        __syncthreads();
    }

    // epilogue: c0,c1 -> (row g, cols 2tg,2tg+1); c2,c3 -> row g+8
    #pragma unroll
    for (int mt = 0; mt < 2; mt++) {
        const int row = m0 + wm * 32 + mt * 16 + g;
        #pragma unroll
        for (int nt = 0; nt < 8; nt++) {
            const int col = n0 + wn * 64 + nt * 8 + 2 * tg;
            const float2 bv = *(const float2*)&bias[col];
            float2 v0 = make_float2(acc[mt][nt][0] + bv.x, acc[mt][nt][1] + bv.y);
            float2 v1 = make_float2(acc[mt][nt][2] + bv.x, acc[mt][nt][3] + bv.y);
            *(float2*)&C[(size_t)row * EMBED + col]       = v0;
            *(float2*)&C[(size_t)(row + 8) * EMBED + col] = v1;
        }
    }
}

// ---------------------------------------------------------------------------
// Kernel 2: Gram partials (fp32, f32x2). Gpart[c][bh][d][e] = sum_s Q.K
// ---------------------------------------------------------------------------
__global__ __launch_bounds__(256, 2)
void gram_kernel()
{
    __shared__ float Qs[64][64];
    __shared__ float Ks[64][64];

    const int bh = blockIdx.x, chunk = blockIdx.y;
    const int b = bh >> 4, h = bh & 15;
    const float* Q = g_QKV[0];
    const float* K = g_QKV[1];
    const size_t base = ((size_t)b * SEQ + (size_t)chunk * SCHUNK) * EMBED + h * DK;

    const int tid = threadIdx.x;
    const int tx = tid & 15, ty = tid >> 4;
    const int lr = tid >> 4, lc4 = (tid & 15) << 2;

    unsigned long long c2[4][2];
    #pragma unroll
    for (int i = 0; i < 4; i++) { c2[i][0] = 0ull; c2[i][1] = 0ull; }

    for (int st = 0; st < SCHUNK / 64; st++) {
        #pragma unroll
        for (int rr = 0; rr < 64; rr += 16) {
            const int s = rr + lr;
            const size_t gg = base + (size_t)(st * 64 + s) * EMBED + lc4;
            *(float4*)&Qs[s][lc4] = *(const float4*)(Q + gg);
            *(float4*)&Ks[s][lc4] = *(const float4*)(K + gg);
        }
        __syncthreads();

        #pragma unroll 8
        for (int ss = 0; ss < 64; ss++) {
            float4 q4 = *(const float4*)&Qs[ss][ty * 4];
            ulonglong2 k2 = *(const ulonglong2*)&Ks[ss][tx * 4];
            float qv[4] = {q4.x, q4.y, q4.z, q4.w};
            #pragma unroll
            for (int i = 0; i < 4; i++) {
                unsigned long long ad = dup2(qv[i]);
                ffma2(c2[i][0], ad, k2.x);
                ffma2(c2[i][1], ad, k2.y);
            }
        }
        __syncthreads();
    }

    float* gp = g_Gpart + ((size_t)chunk * BHEADS + bh) * DK * DK;
    #pragma unroll
    for (int i = 0; i < 4; i++) {
        const int d = ty * 4 + i;
        *(float4*)&gp[d * DK + tx * 4] =
            make_float4(lo2(c2[i][0]), hi2(c2[i][0]), lo2(c2[i][1]), hi2(c2[i][1]));
    }
}

// ---------------------------------------------------------------------------
// Kernel 3: reduce partials + softmax; write attn transposed At[e][d]
// ---------------------------------------------------------------------------
__global__ __launch_bounds__(256)
void softmax_kernel()
{
    const int gwarp = (blockIdx.x * blockDim.x + threadIdx.x) >> 5;
    const int lane = threadIdx.x & 31;
    const int bh = gwarp >> 6;
    const int d = gwarp & 63;

    float g0 = 0.f, g1 = 0.f;
    #pragma unroll
    for (int c = 0; c < NCHUNK; c++) {
        const float* gp = g_Gpart + (((size_t)c * BHEADS + bh) * DK + d) * DK;
        g0 += gp[lane];
        g1 += gp[lane + 32];
    }
    g0 *= 0.125f; g1 *= 0.125f;

    float m = fmaxf(g0, g1);
    #pragma unroll
    for (int o = 16; o > 0; o >>= 1) m = fmaxf(m, __shfl_xor_sync(0xffffffffu, m, o));
    float e0 = expf(g0 - m), e1 = expf(g1 - m);
    float s = e0 + e1;
    #pragma unroll
    for (int o = 16; o > 0; o >>= 1) s += __shfl_xor_sync(0xffffffffu, s, o);
    const float inv = 1.0f / s;

    float* at = g_At + (size_t)bh * DK * DK;
    at[lane * DK + d]        = e0 * inv;
    at[(lane + 32) * DK + d] = e1 * inv;
}

// ---------------------------------------------------------------------------
// Kernel 4: output mix  out[m, h*64+d] = sum_e attn[bh][d][e] * V[m, h*64+e]
// ---------------------------------------------------------------------------
__global__ __launch_bounds__(256, 2)
void out_kernel(float* __restrict__ OUT)
{
    __shared__ float Am[64][64];
    __shared__ float Vt[64][65];

    const int m0 = blockIdx.x * 64;
    const int h  = blockIdx.y;
    const int b  = m0 >> 12;
    const int bh = b * NHEADS + h;
    const float* V = g_QKV[2];

    const int tid = threadIdx.x;
    const int tx = tid & 15, ty = tid >> 4;
    const int lr = tid >> 4, lc4 = (tid & 15) << 2;

    const float* at = g_At + (size_t)bh * DK * DK;
    #pragma unroll
    for (int rr = 0; rr < 64; rr += 16)
        *(float4*)&Am[rr + lr][lc4] = *(const float4*)&at[(rr + lr) * DK + lc4];

    #pragma unroll
    for (int rr = 0; rr < 64; rr += 16) {
        const int s = rr + lr;
        float4 v = *(const float4*)(V + (size_t)(m0 + s) * EMBED + h * DK + lc4);
        Vt[lc4 + 0][s] = v.x;
        Vt[lc4 + 1][s] = v.y;
        Vt[lc4 + 2][s] = v.z;
        Vt[lc4 + 3][s] = v.w;
    }
    __syncthreads();

    unsigned long long o2[4][2];
    #pragma unroll
    for (int i = 0; i < 4; i++) { o2[i][0] = 0ull; o2[i][1] = 0ull; }

    #pragma unroll 8
    for (int ee = 0; ee < 64; ee++) {
        ulonglong2 ap = *(const ulonglong2*)&Am[ee][tx * 4];
        #pragma unroll
        for (int si = 0; si < 4; si++) {
            unsigned long long vd = dup2(Vt[ee][ty * 4 + si]);
            ffma2(o2[si][0], vd, ap.x);
            ffma2(o2[si][1], vd, ap.y);
        }
    }

    #pragma unroll
    for (int si = 0; si < 4; si++) {
        const int m = m0 + ty * 4 + si;
        *(float4*)&OUT[(size_t)m * EMBED + h * DK + tx * 4] =
            make_float4(lo2(o2[si][0]), hi2(o2[si][0]),
                        lo2(o2[si][1]), hi2(o2[si][1]));
    }
}

// ---------------------------------------------------------------------------
// Launch
// ---------------------------------------------------------------------------
extern "C" void kernel_launch(void* const* d_in, const int* in_sizes, int n_in,
                              void* d_out, int out_size)
{
    const float* x  = (const float*)d_in[0];
    const float* Wq = (const float*)d_in[1];
    const float* bq = (const float*)d_in[2];
    const float* Wk = (const float*)d_in[3];
    const float* bk = (const float*)d_in[4];
    const float* Wv = (const float*)d_in[5];
    const float* bv = (const float*)d_in[6];
    float* out = (float*)d_out;

    cudaFuncSetAttribute(gemm_split_kernel,
                         cudaFuncAttributeMaxDynamicSharedMemorySize, G_SMEM);

    __nv_bfloat16 *xh, *xl, *whb, *wlb;
    cudaGetSymbolAddress((void**)&xh,  g_xh);
    cudaGetSymbolAddress((void**)&xl,  g_xl);
    cudaGetSymbolAddress((void**)&whb, g_wh);
    cudaGetSymbolAddress((void**)&wlb, g_wl);
    float* qkv;
    cudaGetSymbolAddress((void**)&qkv, g_QKV);

    __nv_bfloat16* wh[3] = {whb, whb + EMBED * EMBED, whb + 2 * EMBED * EMBED};
    __nv_bfloat16* wl[3] = {wlb, wlb + EMBED * EMBED, wlb + 2 * EMBED * EMBED};

    // 1) hi/lo splits
    split_kernel<<<(MTOK * EMBED) / 1024, 256>>>(x, xh, xl);
    split_kernel<<<(EMBED * EMBED) / 1024, 256>>>(Wq, wh[0], wl[0]);
    split_kernel<<<(EMBED * EMBED) / 1024, 256>>>(Wk, wh[1], wl[1]);
    split_kernel<<<(EMBED * EMBED) / 1024, 256>>>(Wv, wh[2], wl[2]);

    // 2) tensor-core projections (mma.sync + ldmatrix; N fastest for L2 A reuse)
    dim3 ggrid(EMBED / 128, MTOK / 128);   // (8, 256)
    gemm_split_kernel<<<ggrid, 256, G_SMEM>>>(xh, xl, wh[0], wl[0], bq,
                                              qkv + 0ll * MTOK * EMBED);
    gemm_split_kernel<<<ggrid, 256, G_SMEM>>>(xh, xl, wh[1], wl[1], bk,
                                              qkv + 1ll * MTOK * EMBED);
    gemm_split_kernel<<<ggrid, 256, G_SMEM>>>(xh, xl, wh[2], wl[2], bv,
                                              qkv + 2ll * MTOK * EMBED);

    // 3) attention over channels
    gram_kernel<<<dim3(BHEADS, NCHUNK), 256>>>();
    softmax_kernel<<<(BHEADS * DK) / 8, 256>>>();
    out_kernel<<<dim3(MTOK / 64, NHEADS), 256>>>(out);
}

// round 9
// speedup vs baseline: 1.9630x; 1.0166x over previous
#include <cuda_runtime.h>
#include <cuda_bf16.h>
#include <cstdint>

#define EMBED   1024
#define NHEADS  16
#define DK      64
#define BATCH   8
#define SEQ     4096
#define MTOK    (BATCH * SEQ)      /* 32768 tokens */
#define BHEADS  (BATCH * NHEADS)   /* 128 head-instances */
#define NCHUNK  8
#define SCHUNK  (SEQ / NCHUNK)     /* 512 */

// ---------------------------------------------------------------------------
// Scratch (__device__ globals: the sanctioned no-alloc workaround)
// ---------------------------------------------------------------------------
__device__ float g_QKV[3][MTOK * EMBED];                     // fp32 Q,K,V
__device__ float g_Gpart[NCHUNK * BHEADS * DK * DK];         // gram partials
__device__ float g_At[BHEADS * DK * DK];                     // attn transposed [e][d]
__device__ __nv_bfloat16 g_xh[MTOK * EMBED];                 // x hi/lo split
__device__ __nv_bfloat16 g_xl[MTOK * EMBED];
__device__ __nv_bfloat16 g_wh[3][EMBED * EMBED];             // W hi/lo split (q,k,v)
__device__ __nv_bfloat16 g_wl[3][EMBED * EMBED];

// ---------------------------------------------------------------------------
// helpers
// ---------------------------------------------------------------------------
static __device__ __forceinline__ uint32_t smem_u32(const void* p) {
    uint32_t a;
    asm("{ .reg .u64 t; cvta.to.shared.u64 t, %1; cvt.u32.u64 %0, t; }"
        : "=r"(a) : "l"(p));
    return a;
}
static __device__ __forceinline__ void cp16(uint32_t dst, const void* src) {
    asm volatile("cp.async.cg.shared.global [%0], [%1], 16;" :: "r"(dst), "l"(src));
}
#define CP_COMMIT()  asm volatile("cp.async.commit_group;" ::: "memory")
#define CP_WAIT(n)   asm volatile("cp.async.wait_group %0;" :: "n"(n) : "memory")

// mma.sync m16n8k16 row.col f32.bf16.bf16.f32 (baseline sm_80+ path)
static __device__ __forceinline__ void hmma(float* c, const uint32_t* a,
                                            uint32_t b0, uint32_t b1) {
    asm volatile(
        "mma.sync.aligned.m16n8k16.row.col.f32.bf16.bf16.f32 "
        "{%0,%1,%2,%3}, {%4,%5,%6,%7}, {%8,%9}, {%0,%1,%2,%3};"
        : "+f"(c[0]), "+f"(c[1]), "+f"(c[2]), "+f"(c[3])
        : "r"(a[0]), "r"(a[1]), "r"(a[2]), "r"(a[3]), "r"(b0), "r"(b1));
}
// ldmatrix x4: fills 4 fragment regs from 4 8x8 b16 tiles (lane-group addressed)
static __device__ __forceinline__ void ldsm4(uint32_t* r, uint32_t addr) {
    asm volatile("ldmatrix.sync.aligned.m8n8.x4.shared.b16 {%0,%1,%2,%3}, [%4];"
                 : "=r"(r[0]), "=r"(r[1]), "=r"(r[2]), "=r"(r[3]) : "r"(addr));
}

// packed fp32x2 helpers (for the fp32 attention kernels)
__device__ __forceinline__ void ffma2(unsigned long long &d, unsigned long long a,
                                      unsigned long long b) {
    asm("fma.rn.f32x2 %0, %1, %2, %0;" : "+l"(d) : "l"(a), "l"(b));
}
__device__ __forceinline__ unsigned long long dup2(float x) {
    unsigned long long r; unsigned xi = __float_as_uint(x);
    asm("mov.b64 %0, {%1, %1};" : "=l"(r) : "r"(xi));
    return r;
}
__device__ __forceinline__ float lo2(unsigned long long v) {
    return __uint_as_float((unsigned)(v & 0xffffffffull));
}
__device__ __forceinline__ float hi2(unsigned long long v) {
    return __uint_as_float((unsigned)(v >> 32));
}

// ---------------------------------------------------------------------------
// Kernel 0: fp32 -> bf16 hi/lo split. 4 elems per thread.
// ---------------------------------------------------------------------------
__global__ __launch_bounds__(256)
void split_kernel(const float* __restrict__ src, __nv_bfloat16* __restrict__ hi,
                  __nv_bfloat16* __restrict__ lo)
{
    const int i = (blockIdx.x * 256 + threadIdx.x) * 4;
    float4 v = *(const float4*)(src + i);
    __nv_bfloat16 h0 = __float2bfloat16(v.x);
    __nv_bfloat16 h1 = __float2bfloat16(v.y);
    __nv_bfloat16 h2 = __float2bfloat16(v.z);
    __nv_bfloat16 h3 = __float2bfloat16(v.w);
    __nv_bfloat16 l0 = __float2bfloat16(v.x - __bfloat162float(h0));
    __nv_bfloat16 l1 = __float2bfloat16(v.y - __bfloat162float(h1));
    __nv_bfloat16 l2 = __float2bfloat16(v.z - __bfloat162float(h2));
    __nv_bfloat16 l3 = __float2bfloat16(v.w - __bfloat162float(h3));
    __nv_bfloat162 hp0 = {h0, h1}, hp1 = {h2, h3};
    __nv_bfloat162 lp0 = {l0, l1}, lp1 = {l2, l3};
    *(__nv_bfloat162*)(hi + i)     = hp0;
    *(__nv_bfloat162*)(hi + i + 2) = hp1;
    *(__nv_bfloat162*)(lo + i)     = lp0;
    *(__nv_bfloat162*)(lo + i + 2) = lp1;
}

// ---------------------------------------------------------------------------
// Kernel 1: mma.sync projection GEMM, bf16 hi/lo split, ldmatrix fragments.
//   C = Xh*Wh + Xh*Wl + Xl*Wh + bias   (fp32 accumulators)
// CTA tile 128x128, 256 threads (8 warps: 4M x 2N, warp tile 32x64).
// Mainloop emits the three split passes as SEPARATE sweeps so consecutive
// HMMAs never share an accumulator (RAW distance = 16 HMMA).
// ---------------------------------------------------------------------------
#define GBK        32
#define G_NCH      (EMBED / GBK)        /* 32 chunks */
#define PADW       40                   /* bf16 per padded row */
#define ROWB       (PADW * 2)           /* 80 bytes per row */
#define MAT_BYTES  (128 * ROWB)         /* 10240 */
#define STAGE_B    (4 * MAT_BYTES)      /* 40960 */
#define G_SMEM     (2 * STAGE_B)        /* 81920 */

static __device__ __forceinline__ void load_chunk(
    uint32_t sb, int buf, int c, int m0, int n0,
    const __nv_bfloat16* __restrict__ Ah, const __nv_bfloat16* __restrict__ Al,
    const __nv_bfloat16* __restrict__ Bh, const __nv_bfloat16* __restrict__ Bl,
    int tid)
{
    const uint32_t st = sb + buf * STAGE_B;
    #pragma unroll
    for (int i = 0; i < 2; i++) {
        const int slot = i * 256 + tid;          // 0..511
        const int row = slot >> 2;               // 0..127
        const int seg = slot & 3;                // 16B segment (8 bf16)
        const uint32_t d = row * ROWB + seg * 16;
        const size_t gA = (size_t)(m0 + row) * EMBED + c * GBK + seg * 8;
        const size_t gB = (size_t)(n0 + row) * EMBED + c * GBK + seg * 8;
        cp16(st + 0 * MAT_BYTES + d, Ah + gA);
        cp16(st + 1 * MAT_BYTES + d, Al + gA);
        cp16(st + 2 * MAT_BYTES + d, Bh + gB);
        cp16(st + 3 * MAT_BYTES + d, Bl + gB);
    }
    CP_COMMIT();
}

__global__ __launch_bounds__(256, 2)
void gemm_split_kernel(const __nv_bfloat16* __restrict__ Ah,
                       const __nv_bfloat16* __restrict__ Al,
                       const __nv_bfloat16* __restrict__ Bh,
                       const __nv_bfloat16* __restrict__ Bl,
                       const float* __restrict__ bias,
                       float* __restrict__ C)
{
    extern __shared__ char smem[];
    const uint32_t sb = smem_u32(smem);
    const int tid  = threadIdx.x;
    const int wid  = tid >> 5;
    const int lane = tid & 31;
    const int g    = lane >> 2;          // c-fragment row group 0..7
    const int tg   = lane & 3;           // c-fragment col pair 0..3

    const int n0 = blockIdx.x * 128;     // x fastest: CTAs sharing m0 reuse A in L2
    const int m0 = blockIdx.y * 128;

    const int wm = wid & 3;              // 0..3 -> M offset
    const int wn = wid >> 2;             // 0..1 -> N offset

    // ldmatrix per-lane base byte offsets.
    const int grp = lane >> 3, lr8 = lane & 7;
    const uint32_t aoff = (uint32_t)((wm * 32 + (grp & 1) * 8 + lr8) * ROWB
                                     + (grp >> 1) * 16);
    const uint32_t boff = (uint32_t)((wn * 64 + (grp >> 1) * 8 + lr8) * ROWB
                                     + (grp & 1) * 16);

    float acc[2][8][4];
    #pragma unroll
    for (int mt = 0; mt < 2; mt++)
        #pragma unroll
        for (int nt = 0; nt < 8; nt++)
            #pragma unroll
            for (int r = 0; r < 4; r++) acc[mt][nt][r] = 0.f;

    load_chunk(sb, 0, 0, m0, n0, Ah, Al, Bh, Bl, tid);

    for (int c = 0; c < G_NCH; c++) {
        const int buf = c & 1;
        if (c + 1 < G_NCH) {
            load_chunk(sb, buf ^ 1, c + 1, m0, n0, Ah, Al, Bh, Bl, tid);
            CP_WAIT(1);
        } else {
            CP_WAIT(0);
        }
        __syncthreads();

        const uint32_t stAh = sb + buf * STAGE_B;
        const uint32_t stAl = stAh + MAT_BYTES;
        const uint32_t stBh = stAh + 2 * MAT_BYTES;
        const uint32_t stBl = stAh + 3 * MAT_BYTES;

        #pragma unroll
        for (int step = 0; step < 2; step++) {
            const uint32_t so = step * 32;       // 16 bf16 = 32 B along k

            uint32_t ah[2][4], al[2][4];
            #pragma unroll
            for (int mt = 0; mt < 2; mt++) {
                ldsm4(ah[mt], stAh + aoff + mt * (16 * ROWB) + so);
                ldsm4(al[mt], stAl + aoff + mt * (16 * ROWB) + so);
            }

            // ---- pass 0: hi*hi ---- (16 HMMA, all-distinct accumulators)
            #pragma unroll
            for (int pr = 0; pr < 4; pr++) {
                uint32_t b4[4];
                ldsm4(b4, stBh + boff + pr * (16 * ROWB) + so);
                hmma(acc[0][2 * pr],     ah[0], b4[0], b4[1]);
                hmma(acc[0][2 * pr + 1], ah[0], b4[2], b4[3]);
                hmma(acc[1][2 * pr],     ah[1], b4[0], b4[1]);
                hmma(acc[1][2 * pr + 1], ah[1], b4[2], b4[3]);
            }
            // ---- pass 1: hi*lo ----
            #pragma unroll
            for (int pr = 0; pr < 4; pr++) {
                uint32_t b4[4];
                ldsm4(b4, stBl + boff + pr * (16 * ROWB) + so);
                hmma(acc[0][2 * pr],     ah[0], b4[0], b4[1]);
                hmma(acc[0][2 * pr + 1], ah[0], b4[2], b4[3]);
                hmma(acc[1][2 * pr],     ah[1], b4[0], b4[1]);
                hmma(acc[1][2 * pr + 1], ah[1], b4[2], b4[3]);
            }
            // ---- pass 2: lo*hi ----
            #pragma unroll
            for (int pr = 0; pr < 4; pr++) {
                uint32_t b4[4];
                ldsm4(b4, stBh + boff + pr * (16 * ROWB) + so);
                hmma(acc[0][2 * pr],     al[0], b4[0], b4[1]);
                hmma(acc[0][2 * pr + 1], al[0], b4[2], b4[3]);
                hmma(acc[1][2 * pr],     al[1], b4[0], b4[1]);
                hmma(acc[1][2 * pr + 1], al[1], b4[2], b4[3]);
            }
        }
        __syncthreads();
    }

    // epilogue: c0,c1 -> (row g, cols 2tg,2tg+1); c2,c3 -> row g+8
    #pragma unroll
    for (int mt = 0; mt < 2; mt++) {
        const int row = m0 + wm * 32 + mt * 16 + g;
        #pragma unroll
        for (int nt = 0; nt < 8; nt++) {
            const int col = n0 + wn * 64 + nt * 8 + 2 * tg;
            const float2 bv = *(const float2*)&bias[col];
            float2 v0 = make_float2(acc[mt][nt][0] + bv.x, acc[mt][nt][1] + bv.y);
            float2 v1 = make_float2(acc[mt][nt][2] + bv.x, acc[mt][nt][3] + bv.y);
            *(float2*)&C[(size_t)row * EMBED + col]       = v0;
            *(float2*)&C[(size_t)(row + 8) * EMBED + col] = v1;
        }
    }
}

// ---------------------------------------------------------------------------
// Kernel 2: Gram partials (fp32, f32x2). Gpart[c][bh][d][e] = sum_s Q.K
// ---------------------------------------------------------------------------
__global__ __launch_bounds__(256, 2)
void gram_kernel()
{
    __shared__ float Qs[64][64];
    __shared__ float Ks[64][64];

    const int bh = blockIdx.x, chunk = blockIdx.y;
    const int b = bh >> 4, h = bh & 15;
    const float* Q = g_QKV[0];
    const float* K = g_QKV[1];
    const size_t base = ((size_t)b * SEQ + (size_t)chunk * SCHUNK) * EMBED + h * DK;

    const int tid = threadIdx.x;
    const int tx = tid & 15, ty = tid >> 4;
    const int lr = tid >> 4, lc4 = (tid & 15) << 2;

    unsigned long long c2[4][2];
    #pragma unroll
    for (int i = 0; i < 4; i++) { c2[i][0] = 0ull; c2[i][1] = 0ull; }

    for (int st = 0; st < SCHUNK / 64; st++) {
        #pragma unroll
        for (int rr = 0; rr < 64; rr += 16) {
            const int s = rr + lr;
            const size_t gg = base + (size_t)(st * 64 + s) * EMBED + lc4;
            *(float4*)&Qs[s][lc4] = *(const float4*)(Q + gg);
            *(float4*)&Ks[s][lc4] = *(const float4*)(K + gg);
        }
        __syncthreads();

        #pragma unroll 8
        for (int ss = 0; ss < 64; ss++) {
            float4 q4 = *(const float4*)&Qs[ss][ty * 4];
            ulonglong2 k2 = *(const ulonglong2*)&Ks[ss][tx * 4];
            float qv[4] = {q4.x, q4.y, q4.z, q4.w};
            #pragma unroll
            for (int i = 0; i < 4; i++) {
                unsigned long long ad = dup2(qv[i]);
                ffma2(c2[i][0], ad, k2.x);
                ffma2(c2[i][1], ad, k2.y);
            }
        }
        __syncthreads();
    }

    float* gp = g_Gpart + ((size_t)chunk * BHEADS + bh) * DK * DK;
    #pragma unroll
    for (int i = 0; i < 4; i++) {
        const int d = ty * 4 + i;
        *(float4*)&gp[d * DK + tx * 4] =
            make_float4(lo2(c2[i][0]), hi2(c2[i][0]), lo2(c2[i][1]), hi2(c2[i][1]));
    }
}

// ---------------------------------------------------------------------------
// Kernel 3: reduce partials + softmax; write attn transposed At[e][d]
// ---------------------------------------------------------------------------
__global__ __launch_bounds__(256)
void softmax_kernel()
{
    const int gwarp = (blockIdx.x * blockDim.x + threadIdx.x) >> 5;
    const int lane = threadIdx.x & 31;
    const int bh = gwarp >> 6;
    const int d = gwarp & 63;

    float g0 = 0.f, g1 = 0.f;
    #pragma unroll
    for (int c = 0; c < NCHUNK; c++) {
        const float* gp = g_Gpart + (((size_t)c * BHEADS + bh) * DK + d) * DK;
        g0 += gp[lane];
        g1 += gp[lane + 32];
    }
    g0 *= 0.125f; g1 *= 0.125f;

    float m = fmaxf(g0, g1);
    #pragma unroll
    for (int o = 16; o > 0; o >>= 1) m = fmaxf(m, __shfl_xor_sync(0xffffffffu, m, o));
    float e0 = expf(g0 - m), e1 = expf(g1 - m);
    float s = e0 + e1;
    #pragma unroll
    for (int o = 16; o > 0; o >>= 1) s += __shfl_xor_sync(0xffffffffu, s, o);
    const float inv = 1.0f / s;

    float* at = g_At + (size_t)bh * DK * DK;
    at[lane * DK + d]        = e0 * inv;
    at[(lane + 32) * DK + d] = e1 * inv;
}

// ---------------------------------------------------------------------------
// Kernel 4: output mix  out[m, h*64+d] = sum_e attn[bh][d][e] * V[m, h*64+e]
// ---------------------------------------------------------------------------
__global__ __launch_bounds__(256, 2)
void out_kernel(float* __restrict__ OUT)
{
    __shared__ float Am[64][64];
    __shared__ float Vt[64][65];

    const int m0 = blockIdx.x * 64;
    const int h  = blockIdx.y;
    const int b  = m0 >> 12;
    const int bh = b * NHEADS + h;
    const float* V = g_QKV[2];

    const int tid = threadIdx.x;
    const int tx = tid & 15, ty = tid >> 4;
    const int lr = tid >> 4, lc4 = (tid & 15) << 2;

    const float* at = g_At + (size_t)bh * DK * DK;
    #pragma unroll
    for (int rr = 0; rr < 64; rr += 16)
        *(float4*)&Am[rr + lr][lc4] = *(const float4*)&at[(rr + lr) * DK + lc4];

    #pragma unroll
    for (int rr = 0; rr < 64; rr += 16) {
        const int s = rr + lr;
        float4 v = *(const float4*)(V + (size_t)(m0 + s) * EMBED + h * DK + lc4);
        Vt[lc4 + 0][s] = v.x;
        Vt[lc4 + 1][s] = v.y;
        Vt[lc4 + 2][s] = v.z;
        Vt[lc4 + 3][s] = v.w;
    }
    __syncthreads();

    unsigned long long o2[4][2];
    #pragma unroll
    for (int i = 0; i < 4; i++) { o2[i][0] = 0ull; o2[i][1] = 0ull; }

    #pragma unroll 8
    for (int ee = 0; ee < 64; ee++) {
        ulonglong2 ap = *(const ulonglong2*)&Am[ee][tx * 4];
        #pragma unroll
        for (int si = 0; si < 4; si++) {
            unsigned long long vd = dup2(Vt[ee][ty * 4 + si]);
            ffma2(o2[si][0], vd, ap.x);
            ffma2(o2[si][1], vd, ap.y);
        }
    }

    #pragma unroll
    for (int si = 0; si < 4; si++) {
        const int m = m0 + ty * 4 + si;
        *(float4*)&OUT[(size_t)m * EMBED + h * DK + tx * 4] =
            make_float4(lo2(o2[si][0]), hi2(o2[si][0]),
                        lo2(o2[si][1]), hi2(o2[si][1]));
    }
}

// ---------------------------------------------------------------------------
// Launch
// ---------------------------------------------------------------------------
extern "C" void kernel_launch(void* const* d_in, const int* in_sizes, int n_in,
                              void* d_out, int out_size)
{
    const float* x  = (const float*)d_in[0];
    const float* Wq = (const float*)d_in[1];
    const float* bq = (const float*)d_in[2];
    const float* Wk = (const float*)d_in[3];
    const float* bk = (const float*)d_in[4];
    const float* Wv = (const float*)d_in[5];
    const float* bv = (const float*)d_in[6];
    float* out = (float*)d_out;

    cudaFuncSetAttribute(gemm_split_kernel,
                         cudaFuncAttributeMaxDynamicSharedMemorySize, G_SMEM);

    __nv_bfloat16 *xh, *xl, *whb, *wlb;
    cudaGetSymbolAddress((void**)&xh,  g_xh);
    cudaGetSymbolAddress((void**)&xl,  g_xl);
    cudaGetSymbolAddress((void**)&whb, g_wh);
    cudaGetSymbolAddress((void**)&wlb, g_wl);
    float* qkv;
    cudaGetSymbolAddress((void**)&qkv, g_QKV);

    __nv_bfloat16* wh[3] = {whb, whb + EMBED * EMBED, whb + 2 * EMBED * EMBED};
    __nv_bfloat16* wl[3] = {wlb, wlb + EMBED * EMBED, wlb + 2 * EMBED * EMBED};

    // 1) hi/lo splits
    split_kernel<<<(MTOK * EMBED) / 1024, 256>>>(x, xh, xl);
    split_kernel<<<(EMBED * EMBED) / 1024, 256>>>(Wq, wh[0], wl[0]);
    split_kernel<<<(EMBED * EMBED) / 1024, 256>>>(Wk, wh[1], wl[1]);
    split_kernel<<<(EMBED * EMBED) / 1024, 256>>>(Wv, wh[2], wl[2]);

    // 2) tensor-core projections (mma.sync + ldmatrix; N fastest for L2 A reuse)
    dim3 ggrid(EMBED / 128, MTOK / 128);   // (8, 256)
    gemm_split_kernel<<<ggrid, 256, G_SMEM>>>(xh, xl, wh[0], wl[0], bq,
                                              qkv + 0ll * MTOK * EMBED);
    gemm_split_kernel<<<ggrid, 256, G_SMEM>>>(xh, xl, wh[1], wl[1], bk,
                                              qkv + 1ll * MTOK * EMBED);
    gemm_split_kernel<<<ggrid, 256, G_SMEM>>>(xh, xl, wh[2], wl[2], bv,
                                              qkv + 2ll * MTOK * EMBED);

    // 3) attention over channels
    gram_kernel<<<dim3(BHEADS, NCHUNK), 256>>>();
    softmax_kernel<<<(BHEADS * DK) / 8, 256>>>();
    out_kernel<<<dim3(MTOK / 64, NHEADS), 256>>>(out);
}

// round 10
// speedup vs baseline: 2.6203x; 1.3348x over previous
#include <cuda_runtime.h>
#include <cuda_bf16.h>
#include <cuda_fp16.h>
#include <cstdint>

#define EMBED   1024
#define NHEADS  16
#define DK      64
#define BATCH   8
#define SEQ     4096
#define MTOK    (BATCH * SEQ)      /* 32768 tokens */
#define BHEADS  (BATCH * NHEADS)   /* 128 head-instances */
#define NCHUNK  8
#define SCHUNK  (SEQ / NCHUNK)     /* 512 */

// ---------------------------------------------------------------------------
// Scratch (__device__ globals: the sanctioned no-alloc workaround)
// ---------------------------------------------------------------------------
__device__ float g_QKV[3][MTOK * EMBED];                     // fp32 Q,K,V
__device__ float g_Gpart[NCHUNK * BHEADS * DK * DK];         // gram partials
__device__ float g_At[BHEADS * DK * DK];                     // attn transposed [e][d]
__device__ __half g_xh[MTOK * EMBED];                        // x fp16 hi
__device__ __half g_xl[MTOK * EMBED];                        // x fp16 lo (residual)
__device__ __half g_w[3][EMBED * EMBED];                     // W fp16 (q,k,v)

// ---------------------------------------------------------------------------
// helpers
// ---------------------------------------------------------------------------
static __device__ __forceinline__ uint32_t smem_u32(const void* p) {
    uint32_t a;
    asm("{ .reg .u64 t; cvta.to.shared.u64 t, %1; cvt.u32.u64 %0, t; }"
        : "=r"(a) : "l"(p));
    return a;
}
static __device__ __forceinline__ void cp16(uint32_t dst, const void* src) {
    asm volatile("cp.async.cg.shared.global [%0], [%1], 16;" :: "r"(dst), "l"(src));
}
#define CP_COMMIT()  asm volatile("cp.async.commit_group;" ::: "memory")
#define CP_WAIT(n)   asm volatile("cp.async.wait_group %0;" :: "n"(n) : "memory")

// mma.sync m16n8k16 row.col f32.f16.f16.f32 (baseline sm_80+ path)
static __device__ __forceinline__ void hmma(float* c, const uint32_t* a,
                                            uint32_t b0, uint32_t b1) {
    asm volatile(
        "mma.sync.aligned.m16n8k16.row.col.f32.f16.f16.f32 "
        "{%0,%1,%2,%3}, {%4,%5,%6,%7}, {%8,%9}, {%0,%1,%2,%3};"
        : "+f"(c[0]), "+f"(c[1]), "+f"(c[2]), "+f"(c[3])
        : "r"(a[0]), "r"(a[1]), "r"(a[2]), "r"(a[3]), "r"(b0), "r"(b1));
}
// ldmatrix x4: fills 4 fragment regs from 4 8x8 b16 tiles (lane-group addressed)
static __device__ __forceinline__ void ldsm4(uint32_t* r, uint32_t addr) {
    asm volatile("ldmatrix.sync.aligned.m8n8.x4.shared.b16 {%0,%1,%2,%3}, [%4];"
                 : "=r"(r[0]), "=r"(r[1]), "=r"(r[2]), "=r"(r[3]) : "r"(addr));
}

// packed fp32x2 helpers (for the fp32 attention kernels)
__device__ __forceinline__ void ffma2(unsigned long long &d, unsigned long long a,
                                      unsigned long long b) {
    asm("fma.rn.f32x2 %0, %1, %2, %0;" : "+l"(d) : "l"(a), "l"(b));
}
__device__ __forceinline__ unsigned long long dup2(float x) {
    unsigned long long r; unsigned xi = __float_as_uint(x);
    asm("mov.b64 %0, {%1, %1};" : "=l"(r) : "r"(xi));
    return r;
}
__device__ __forceinline__ float lo2(unsigned long long v) {
    return __uint_as_float((unsigned)(v & 0xffffffffull));
}
__device__ __forceinline__ float hi2(unsigned long long v) {
    return __uint_as_float((unsigned)(v >> 32));
}

// ---------------------------------------------------------------------------
// Kernel 0a: fp32 -> fp16 hi/lo split (for x). 4 elems per thread.
// ---------------------------------------------------------------------------
__global__ __launch_bounds__(256)
void split_x_kernel(const float* __restrict__ src, __half* __restrict__ hi,
                    __half* __restrict__ lo)
{
    const int i = (blockIdx.x * 256 + threadIdx.x) * 4;
    float4 v = *(const float4*)(src + i);
    __half h0 = __float2half_rn(v.x);
    __half h1 = __float2half_rn(v.y);
    __half h2 = __float2half_rn(v.z);
    __half h3 = __float2half_rn(v.w);
    __half l0 = __float2half_rn(v.x - __half2float(h0));
    __half l1 = __float2half_rn(v.y - __half2float(h1));
    __half l2 = __float2half_rn(v.z - __half2float(h2));
    __half l3 = __float2half_rn(v.w - __half2float(h3));
    __half2 hp0 = {h0, h1}, hp1 = {h2, h3};
    __half2 lp0 = {l0, l1}, lp1 = {l2, l3};
    *(__half2*)(hi + i)     = hp0;
    *(__half2*)(hi + i + 2) = hp1;
    *(__half2*)(lo + i)     = lp0;
    *(__half2*)(lo + i + 2) = lp1;
}

// ---------------------------------------------------------------------------
// Kernel 0b: fp32 -> fp16 convert (for W). 4 elems per thread.
// ---------------------------------------------------------------------------
__global__ __launch_bounds__(256)
void cvt_w_kernel(const float* __restrict__ src, __half* __restrict__ dst)
{
    const int i = (blockIdx.x * 256 + threadIdx.x) * 4;
    float4 v = *(const float4*)(src + i);
    __half2 p0 = {__float2half_rn(v.x), __float2half_rn(v.y)};
    __half2 p1 = {__float2half_rn(v.z), __float2half_rn(v.w)};
    *(__half2*)(dst + i)     = p0;
    *(__half2*)(dst + i + 2) = p1;
}

// ---------------------------------------------------------------------------
// Kernel 1: mma.sync projection GEMM, fp16 X hi/lo split, single fp16 W.
//   C = (Xh + Xl) * W^T + bias    (2 HMMA passes, fp32 accumulators)
// CTA tile 128x128, 256 threads (8 warps: 4M x 2N, warp tile 32x64).
// Stage = Xh(10K) + Xl(10K) + W(10K); double-buffered (60K dynamic smem).
// ---------------------------------------------------------------------------
#define GBK        32
#define G_NCH      (EMBED / GBK)        /* 32 chunks */
#define PADW       40                   /* fp16 per padded row */
#define ROWB       (PADW * 2)           /* 80 bytes per row */
#define MAT_BYTES  (128 * ROWB)         /* 10240 */
#define STAGE_B    (3 * MAT_BYTES)      /* 30720 */
#define G_SMEM     (2 * STAGE_B)        /* 61440 */

static __device__ __forceinline__ void load_chunk(
    uint32_t sb, int buf, int c, int m0, int n0,
    const __half* __restrict__ Ah, const __half* __restrict__ Al,
    const __half* __restrict__ B, int tid)
{
    const uint32_t st = sb + buf * STAGE_B;
    #pragma unroll
    for (int i = 0; i < 2; i++) {
        const int slot = i * 256 + tid;          // 0..511
        const int row = slot >> 2;               // 0..127
        const int seg = slot & 3;                // 16B segment (8 fp16)
        const uint32_t d = row * ROWB + seg * 16;
        const size_t gA = (size_t)(m0 + row) * EMBED + c * GBK + seg * 8;
        const size_t gB = (size_t)(n0 + row) * EMBED + c * GBK + seg * 8;
        cp16(st + 0 * MAT_BYTES + d, Ah + gA);
        cp16(st + 1 * MAT_BYTES + d, Al + gA);
        cp16(st + 2 * MAT_BYTES + d, B + gB);
    }
    CP_COMMIT();
}

__global__ __launch_bounds__(256, 2)
void gemm_split_kernel(const __half* __restrict__ Ah,
                       const __half* __restrict__ Al,
                       const __half* __restrict__ B,
                       const float* __restrict__ bias,
                       float* __restrict__ C)
{
    extern __shared__ char smem[];
    const uint32_t sb = smem_u32(smem);
    const int tid  = threadIdx.x;
    const int wid  = tid >> 5;
    const int lane = tid & 31;
    const int g    = lane >> 2;          // c-fragment row group 0..7
    const int tg   = lane & 3;           // c-fragment col pair 0..3

    const int n0 = blockIdx.x * 128;     // x fastest: CTAs sharing m0 reuse A in L2
    const int m0 = blockIdx.y * 128;

    const int wm = wid & 3;              // 0..3 -> M offset
    const int wn = wid >> 2;             // 0..1 -> N offset

    // ldmatrix per-lane base byte offsets.
    const int grp = lane >> 3, lr8 = lane & 7;
    const uint32_t aoff = (uint32_t)((wm * 32 + (grp & 1) * 8 + lr8) * ROWB
                                     + (grp >> 1) * 16);
    const uint32_t boff = (uint32_t)((wn * 64 + (grp >> 1) * 8 + lr8) * ROWB
                                     + (grp & 1) * 16);

    float acc[2][8][4];
    #pragma unroll
    for (int mt = 0; mt < 2; mt++)
        #pragma unroll
        for (int nt = 0; nt < 8; nt++)
            #pragma unroll
            for (int r = 0; r < 4; r++) acc[mt][nt][r] = 0.f;

    load_chunk(sb, 0, 0, m0, n0, Ah, Al, B, tid);

    for (int c = 0; c < G_NCH; c++) {
        const int buf = c & 1;
        if (c + 1 < G_NCH) {
            load_chunk(sb, buf ^ 1, c + 1, m0, n0, Ah, Al, B, tid);
            CP_WAIT(1);
        } else {
            CP_WAIT(0);
        }
        __syncthreads();

        const uint32_t stAh = sb + buf * STAGE_B;
        const uint32_t stAl = stAh + MAT_BYTES;
        const uint32_t stB  = stAh + 2 * MAT_BYTES;

        #pragma unroll
        for (int step = 0; step < 2; step++) {
            const uint32_t so = step * 32;       // 16 fp16 = 32 B along k

            uint32_t ah[2][4], al[2][4];
            #pragma unroll
            for (int mt = 0; mt < 2; mt++) {
                ldsm4(ah[mt], stAh + aoff + mt * (16 * ROWB) + so);
                ldsm4(al[mt], stAl + aoff + mt * (16 * ROWB) + so);
            }

            // ---- pass 0: xh * W ---- (16 HMMA, all-distinct accumulators)
            #pragma unroll
            for (int pr = 0; pr < 4; pr++) {
                uint32_t b4[4];
                ldsm4(b4, stB + boff + pr * (16 * ROWB) + so);
                hmma(acc[0][2 * pr],     ah[0], b4[0], b4[1]);
                hmma(acc[0][2 * pr + 1], ah[0], b4[2], b4[3]);
                hmma(acc[1][2 * pr],     ah[1], b4[0], b4[1]);
                hmma(acc[1][2 * pr + 1], ah[1], b4[2], b4[3]);
            }
            // ---- pass 1: xl * W ----
            #pragma unroll
            for (int pr = 0; pr < 4; pr++) {
                uint32_t b4[4];
                ldsm4(b4, stB + boff + pr * (16 * ROWB) + so);
                hmma(acc[0][2 * pr],     al[0], b4[0], b4[1]);
                hmma(acc[0][2 * pr + 1], al[0], b4[2], b4[3]);
                hmma(acc[1][2 * pr],     al[1], b4[0], b4[1]);
                hmma(acc[1][2 * pr + 1], al[1], b4[2], b4[3]);
            }
        }
        __syncthreads();
    }

    // epilogue: c0,c1 -> (row g, cols 2tg,2tg+1); c2,c3 -> row g+8
    #pragma unroll
    for (int mt = 0; mt < 2; mt++) {
        const int row = m0 + wm * 32 + mt * 16 + g;
        #pragma unroll
        for (int nt = 0; nt < 8; nt++) {
            const int col = n0 + wn * 64 + nt * 8 + 2 * tg;
            const float2 bv = *(const float2*)&bias[col];
            float2 v0 = make_float2(acc[mt][nt][0] + bv.x, acc[mt][nt][1] + bv.y);
            float2 v1 = make_float2(acc[mt][nt][2] + bv.x, acc[mt][nt][3] + bv.y);
            *(float2*)&C[(size_t)row * EMBED + col]       = v0;
            *(float2*)&C[(size_t)(row + 8) * EMBED + col] = v1;
        }
    }
}

// ---------------------------------------------------------------------------
// Kernel 2: Gram partials (fp32, f32x2). Gpart[c][bh][d][e] = sum_s Q.K
// ---------------------------------------------------------------------------
__global__ __launch_bounds__(256, 2)
void gram_kernel()
{
    __shared__ float Qs[64][64];
    __shared__ float Ks[64][64];

    const int bh = blockIdx.x, chunk = blockIdx.y;
    const int b = bh >> 4, h = bh & 15;
    const float* Q = g_QKV[0];
    const float* K = g_QKV[1];
    const size_t base = ((size_t)b * SEQ + (size_t)chunk * SCHUNK) * EMBED + h * DK;

    const int tid = threadIdx.x;
    const int tx = tid & 15, ty = tid >> 4;
    const int lr = tid >> 4, lc4 = (tid & 15) << 2;

    unsigned long long c2[4][2];
    #pragma unroll
    for (int i = 0; i < 4; i++) { c2[i][0] = 0ull; c2[i][1] = 0ull; }

    for (int st = 0; st < SCHUNK / 64; st++) {
        #pragma unroll
        for (int rr = 0; rr < 64; rr += 16) {
            const int s = rr + lr;
            const size_t gg = base + (size_t)(st * 64 + s) * EMBED + lc4;
            *(float4*)&Qs[s][lc4] = *(const float4*)(Q + gg);
            *(float4*)&Ks[s][lc4] = *(const float4*)(K + gg);
        }
        __syncthreads();

        #pragma unroll 8
        for (int ss = 0; ss < 64; ss++) {
            float4 q4 = *(const float4*)&Qs[ss][ty * 4];
            ulonglong2 k2 = *(const ulonglong2*)&Ks[ss][tx * 4];
            float qv[4] = {q4.x, q4.y, q4.z, q4.w};
            #pragma unroll
            for (int i = 0; i < 4; i++) {
                unsigned long long ad = dup2(qv[i]);
                ffma2(c2[i][0], ad, k2.x);
                ffma2(c2[i][1], ad, k2.y);
            }
        }
        __syncthreads();
    }

    float* gp = g_Gpart + ((size_t)chunk * BHEADS + bh) * DK * DK;
    #pragma unroll
    for (int i = 0; i < 4; i++) {
        const int d = ty * 4 + i;
        *(float4*)&gp[d * DK + tx * 4] =
            make_float4(lo2(c2[i][0]), hi2(c2[i][0]), lo2(c2[i][1]), hi2(c2[i][1]));
    }
}

// ---------------------------------------------------------------------------
// Kernel 3: reduce partials + softmax; write attn transposed At[e][d]
// ---------------------------------------------------------------------------
__global__ __launch_bounds__(256)
void softmax_kernel()
{
    const int gwarp = (blockIdx.x * blockDim.x + threadIdx.x) >> 5;
    const int lane = threadIdx.x & 31;
    const int bh = gwarp >> 6;
    const int d = gwarp & 63;

    float g0 = 0.f, g1 = 0.f;
    #pragma unroll
    for (int c = 0; c < NCHUNK; c++) {
        const float* gp = g_Gpart + (((size_t)c * BHEADS + bh) * DK + d) * DK;
        g0 += gp[lane];
        g1 += gp[lane + 32];
    }
    g0 *= 0.125f; g1 *= 0.125f;

    float m = fmaxf(g0, g1);
    #pragma unroll
    for (int o = 16; o > 0; o >>= 1) m = fmaxf(m, __shfl_xor_sync(0xffffffffu, m, o));
    float e0 = expf(g0 - m), e1 = expf(g1 - m);
    float s = e0 + e1;
    #pragma unroll
    for (int o = 16; o > 0; o >>= 1) s += __shfl_xor_sync(0xffffffffu, s, o);
    const float inv = 1.0f / s;

    float* at = g_At + (size_t)bh * DK * DK;
    at[lane * DK + d]        = e0 * inv;
    at[(lane + 32) * DK + d] = e1 * inv;
}

// ---------------------------------------------------------------------------
// Kernel 4: output mix  out[m, h*64+d] = sum_e attn[bh][d][e] * V[m, h*64+e]
// ---------------------------------------------------------------------------
__global__ __launch_bounds__(256, 2)
void out_kernel(float* __restrict__ OUT)
{
    __shared__ float Am[64][64];
    __shared__ float Vt[64][65];

    const int m0 = blockIdx.x * 64;
    const int h  = blockIdx.y;
    const int b  = m0 >> 12;
    const int bh = b * NHEADS + h;
    const float* V = g_QKV[2];

    const int tid = threadIdx.x;
    const int tx = tid & 15, ty = tid >> 4;
    const int lr = tid >> 4, lc4 = (tid & 15) << 2;

    const float* at = g_At + (size_t)bh * DK * DK;
    #pragma unroll
    for (int rr = 0; rr < 64; rr += 16)
        *(float4*)&Am[rr + lr][lc4] = *(const float4*)&at[(rr + lr) * DK + lc4];

    #pragma unroll
    for (int rr = 0; rr < 64; rr += 16) {
        const int s = rr + lr;
        float4 v = *(const float4*)(V + (size_t)(m0 + s) * EMBED + h * DK + lc4);
        Vt[lc4 + 0][s] = v.x;
        Vt[lc4 + 1][s] = v.y;
        Vt[lc4 + 2][s] = v.z;
        Vt[lc4 + 3][s] = v.w;
    }
    __syncthreads();

    unsigned long long o2[4][2];
    #pragma unroll
    for (int i = 0; i < 4; i++) { o2[i][0] = 0ull; o2[i][1] = 0ull; }

    #pragma unroll 8
    for (int ee = 0; ee < 64; ee++) {
        ulonglong2 ap = *(const ulonglong2*)&Am[ee][tx * 4];
        #pragma unroll
        for (int si = 0; si < 4; si++) {
            unsigned long long vd = dup2(Vt[ee][ty * 4 + si]);
            ffma2(o2[si][0], vd, ap.x);
            ffma2(o2[si][1], vd, ap.y);
        }
    }

    #pragma unroll
    for (int si = 0; si < 4; si++) {
        const int m = m0 + ty * 4 + si;
        *(float4*)&OUT[(size_t)m * EMBED + h * DK + tx * 4] =
            make_float4(lo2(o2[si][0]), hi2(o2[si][0]),
                        lo2(o2[si][1]), hi2(o2[si][1]));
    }
}

// ---------------------------------------------------------------------------
// Launch
// ---------------------------------------------------------------------------
extern "C" void kernel_launch(void* const* d_in, const int* in_sizes, int n_in,
                              void* d_out, int out_size)
{
    const float* x  = (const float*)d_in[0];
    const float* Wq = (const float*)d_in[1];
    const float* bq = (const float*)d_in[2];
    const float* Wk = (const float*)d_in[3];
    const float* bk = (const float*)d_in[4];
    const float* Wv = (const float*)d_in[5];
    const float* bv = (const float*)d_in[6];
    float* out = (float*)d_out;

    cudaFuncSetAttribute(gemm_split_kernel,
                         cudaFuncAttributeMaxDynamicSharedMemorySize, G_SMEM);

    __half *xh, *xl, *wb;
    cudaGetSymbolAddress((void**)&xh, g_xh);
    cudaGetSymbolAddress((void**)&xl, g_xl);
    cudaGetSymbolAddress((void**)&wb, g_w);
    float* qkv;
    cudaGetSymbolAddress((void**)&qkv, g_QKV);

    __half* w[3] = {wb, wb + EMBED * EMBED, wb + 2 * EMBED * EMBED};

    // 1) conversions
    split_x_kernel<<<(MTOK * EMBED) / 1024, 256>>>(x, xh, xl);
    cvt_w_kernel<<<(EMBED * EMBED) / 1024, 256>>>(Wq, w[0]);
    cvt_w_kernel<<<(EMBED * EMBED) / 1024, 256>>>(Wk, w[1]);
    cvt_w_kernel<<<(EMBED * EMBED) / 1024, 256>>>(Wv, w[2]);

    // 2) tensor-core projections (2-pass fp16 split; N fastest for L2 A reuse)
    dim3 ggrid(EMBED / 128, MTOK / 128);   // (8, 256)
    gemm_split_kernel<<<ggrid, 256, G_SMEM>>>(xh, xl, w[0], bq,
                                              qkv + 0ll * MTOK * EMBED);
    gemm_split_kernel<<<ggrid, 256, G_SMEM>>>(xh, xl, w[1], bk,
                                              qkv + 1ll * MTOK * EMBED);
    gemm_split_kernel<<<ggrid, 256, G_SMEM>>>(xh, xl, w[2], bv,
                                              qkv + 2ll * MTOK * EMBED);

    // 3) attention over channels
    gram_kernel<<<dim3(BHEADS, NCHUNK), 256>>>();
    softmax_kernel<<<(BHEADS * DK) / 8, 256>>>();
    out_kernel<<<dim3(MTOK / 64, NHEADS), 256>>>(out);
}

// round 11
// speedup vs baseline: 2.6677x; 1.0181x over previous
#include <cuda_runtime.h>
#include <cuda_bf16.h>
#include <cuda_fp16.h>
#include <cstdint>

#define EMBED   1024
#define NHEADS  16
#define DK      64
#define BATCH   8
#define SEQ     4096
#define MTOK    (BATCH * SEQ)      /* 32768 tokens */
#define BHEADS  (BATCH * NHEADS)   /* 128 head-instances */
#define NCHUNK  8
#define SCHUNK  (SEQ / NCHUNK)     /* 512 */

// ---------------------------------------------------------------------------
// Scratch (__device__ globals: the sanctioned no-alloc workaround)
// ---------------------------------------------------------------------------
__device__ float g_QKV[3][MTOK * EMBED];                     // fp32 Q,K,V
__device__ float g_Gpart[NCHUNK * BHEADS * DK * DK];         // gram partials
__device__ float g_At[BHEADS * DK * DK];                     // attn transposed [e][d]
__device__ __half g_xh[MTOK * EMBED];                        // x fp16 hi
__device__ __half g_xl[MTOK * EMBED];                        // x fp16 lo (residual)
__device__ __half g_w[3][EMBED * EMBED];                     // W fp16 (q,k,v)

// ---------------------------------------------------------------------------
// helpers
// ---------------------------------------------------------------------------
static __device__ __forceinline__ uint32_t smem_u32(const void* p) {
    uint32_t a;
    asm("{ .reg .u64 t; cvta.to.shared.u64 t, %1; cvt.u32.u64 %0, t; }"
        : "=r"(a) : "l"(p));
    return a;
}
static __device__ __forceinline__ void cp16(uint32_t dst, const void* src) {
    asm volatile("cp.async.cg.shared.global [%0], [%1], 16;" :: "r"(dst), "l"(src));
}
#define CP_COMMIT()  asm volatile("cp.async.commit_group;" ::: "memory")
#define CP_WAIT(n)   asm volatile("cp.async.wait_group %0;" :: "n"(n) : "memory")

// mma.sync m16n8k16 row.col f32.f16.f16.f32 (baseline sm_80+ path)
static __device__ __forceinline__ void hmma(float* c, const uint32_t* a,
                                            uint32_t b0, uint32_t b1) {
    asm volatile(
        "mma.sync.aligned.m16n8k16.row.col.f32.f16.f16.f32 "
        "{%0,%1,%2,%3}, {%4,%5,%6,%7}, {%8,%9}, {%0,%1,%2,%3};"
        : "+f"(c[0]), "+f"(c[1]), "+f"(c[2]), "+f"(c[3])
        : "r"(a[0]), "r"(a[1]), "r"(a[2]), "r"(a[3]), "r"(b0), "r"(b1));
}
// ldmatrix x4: fills 4 fragment regs from 4 8x8 b16 tiles (lane-group addressed)
static __device__ __forceinline__ void ldsm4(uint32_t* r, uint32_t addr) {
    asm volatile("ldmatrix.sync.aligned.m8n8.x4.shared.b16 {%0,%1,%2,%3}, [%4];"
                 : "=r"(r[0]), "=r"(r[1]), "=r"(r[2]), "=r"(r[3]) : "r"(addr));
}

// packed fp32x2 helpers (for the fp32 attention kernels)
__device__ __forceinline__ void ffma2(unsigned long long &d, unsigned long long a,
                                      unsigned long long b) {
    asm("fma.rn.f32x2 %0, %1, %2, %0;" : "+l"(d) : "l"(a), "l"(b));
}
__device__ __forceinline__ unsigned long long dup2(float x) {
    unsigned long long r; unsigned xi = __float_as_uint(x);
    asm("mov.b64 %0, {%1, %1};" : "=l"(r) : "r"(xi));
    return r;
}
__device__ __forceinline__ float lo2(unsigned long long v) {
    return __uint_as_float((unsigned)(v & 0xffffffffull));
}
__device__ __forceinline__ float hi2(unsigned long long v) {
    return __uint_as_float((unsigned)(v >> 32));
}

// ---------------------------------------------------------------------------
// GEMM configuration (shared by standalone + fused kernels)
// ---------------------------------------------------------------------------
#define GBK        32
#define G_NCH      (EMBED / GBK)        /* 32 chunks */
#define PADW       40                   /* fp16 per padded row */
#define ROWB       (PADW * 2)           /* 80 bytes per row */
#define MAT_BYTES  (128 * ROWB)         /* 10240 */
#define STAGE_B    (3 * MAT_BYTES)      /* 30720 */
#define G_SMEM     (2 * STAGE_B)        /* 61440 */
#define GEMM_BLOCKS (EMBED / 128 * (MTOK / 128))   /* 8 * 256 = 2048 */
#define GRAM_BLOCKS (BHEADS * NCHUNK)              /* 1024 */

static __device__ __forceinline__ void load_chunk(
    uint32_t sb, int buf, int c, int m0, int n0,
    const __half* __restrict__ Ah, const __half* __restrict__ Al,
    const __half* __restrict__ B, int tid)
{
    const uint32_t st = sb + buf * STAGE_B;
    #pragma unroll
    for (int i = 0; i < 2; i++) {
        const int slot = i * 256 + tid;          // 0..511
        const int row = slot >> 2;               // 0..127
        const int seg = slot & 3;                // 16B segment (8 fp16)
        const uint32_t d = row * ROWB + seg * 16;
        const size_t gA = (size_t)(m0 + row) * EMBED + c * GBK + seg * 8;
        const size_t gB = (size_t)(n0 + row) * EMBED + c * GBK + seg * 8;
        cp16(st + 0 * MAT_BYTES + d, Ah + gA);
        cp16(st + 1 * MAT_BYTES + d, Al + gA);
        cp16(st + 2 * MAT_BYTES + d, B + gB);
    }
    CP_COMMIT();
}

// GEMM body: C = (Xh + Xl) * W^T + bias  (2 HMMA passes, fp32 accumulators)
static __device__ __forceinline__ void gemm_body(
    char* smem, int bx,
    const __half* __restrict__ Ah, const __half* __restrict__ Al,
    const __half* __restrict__ B, const float* __restrict__ bias,
    float* __restrict__ C)
{
    const uint32_t sb = smem_u32(smem);
    const int tid  = threadIdx.x;
    const int wid  = tid >> 5;
    const int lane = tid & 31;
    const int g    = lane >> 2;          // c-fragment row group 0..7
    const int tg   = lane & 3;           // c-fragment col pair 0..3

    const int n0 = (bx & 7) * 128;       // n fastest: CTAs sharing m0 reuse A in L2
    const int m0 = (bx >> 3) * 128;

    const int wm = wid & 3;              // 0..3 -> M offset
    const int wn = wid >> 2;             // 0..1 -> N offset

    const int grp = lane >> 3, lr8 = lane & 7;
    const uint32_t aoff = (uint32_t)((wm * 32 + (grp & 1) * 8 + lr8) * ROWB
                                     + (grp >> 1) * 16);
    const uint32_t boff = (uint32_t)((wn * 64 + (grp >> 1) * 8 + lr8) * ROWB
                                     + (grp & 1) * 16);

    float acc[2][8][4];
    #pragma unroll
    for (int mt = 0; mt < 2; mt++)
        #pragma unroll
        for (int nt = 0; nt < 8; nt++)
            #pragma unroll
            for (int r = 0; r < 4; r++) acc[mt][nt][r] = 0.f;

    load_chunk(sb, 0, 0, m0, n0, Ah, Al, B, tid);

    for (int c = 0; c < G_NCH; c++) {
        const int buf = c & 1;
        if (c + 1 < G_NCH) {
            load_chunk(sb, buf ^ 1, c + 1, m0, n0, Ah, Al, B, tid);
            CP_WAIT(1);
        } else {
            CP_WAIT(0);
        }
        __syncthreads();

        const uint32_t stAh = sb + buf * STAGE_B;
        const uint32_t stAl = stAh + MAT_BYTES;
        const uint32_t stB  = stAh + 2 * MAT_BYTES;

        #pragma unroll
        for (int step = 0; step < 2; step++) {
            const uint32_t so = step * 32;       // 16 fp16 = 32 B along k

            uint32_t ah[2][4], al[2][4];
            #pragma unroll
            for (int mt = 0; mt < 2; mt++) {
                ldsm4(ah[mt], stAh + aoff + mt * (16 * ROWB) + so);
                ldsm4(al[mt], stAl + aoff + mt * (16 * ROWB) + so);
            }

            // pass 0: xh * W (16 HMMA, all-distinct accumulators)
            #pragma unroll
            for (int pr = 0; pr < 4; pr++) {
                uint32_t b4[4];
                ldsm4(b4, stB + boff + pr * (16 * ROWB) + so);
                hmma(acc[0][2 * pr],     ah[0], b4[0], b4[1]);
                hmma(acc[0][2 * pr + 1], ah[0], b4[2], b4[3]);
                hmma(acc[1][2 * pr],     ah[1], b4[0], b4[1]);
                hmma(acc[1][2 * pr + 1], ah[1], b4[2], b4[3]);
            }
            // pass 1: xl * W
            #pragma unroll
            for (int pr = 0; pr < 4; pr++) {
                uint32_t b4[4];
                ldsm4(b4, stB + boff + pr * (16 * ROWB) + so);
                hmma(acc[0][2 * pr],     al[0], b4[0], b4[1]);
                hmma(acc[0][2 * pr + 1], al[0], b4[2], b4[3]);
                hmma(acc[1][2 * pr],     al[1], b4[0], b4[1]);
                hmma(acc[1][2 * pr + 1], al[1], b4[2], b4[3]);
            }
        }
        __syncthreads();
    }

    #pragma unroll
    for (int mt = 0; mt < 2; mt++) {
        const int row = m0 + wm * 32 + mt * 16 + g;
        #pragma unroll
        for (int nt = 0; nt < 8; nt++) {
            const int col = n0 + wn * 64 + nt * 8 + 2 * tg;
            const float2 bv = *(const float2*)&bias[col];
            float2 v0 = make_float2(acc[mt][nt][0] + bv.x, acc[mt][nt][1] + bv.y);
            float2 v1 = make_float2(acc[mt][nt][2] + bv.x, acc[mt][nt][3] + bv.y);
            *(float2*)&C[(size_t)row * EMBED + col]       = v0;
            *(float2*)&C[(size_t)(row + 8) * EMBED + col] = v1;
        }
    }
}

// Gram body: Gpart[c][bh][d][e] = sum_{s in chunk} Q.K  (fp32, f32x2)
static __device__ __forceinline__ void gram_body(char* smem, int bh, int chunk)
{
    float (*Qs)[64] = (float(*)[64])smem;
    float (*Ks)[64] = (float(*)[64])(smem + 64 * 64 * 4);

    const int b = bh >> 4, h = bh & 15;
    const float* Q = g_QKV[0];
    const float* K = g_QKV[1];
    const size_t base = ((size_t)b * SEQ + (size_t)chunk * SCHUNK) * EMBED + h * DK;

    const int tid = threadIdx.x;
    const int tx = tid & 15, ty = tid >> 4;
    const int lr = tid >> 4, lc4 = (tid & 15) << 2;

    unsigned long long c2[4][2];
    #pragma unroll
    for (int i = 0; i < 4; i++) { c2[i][0] = 0ull; c2[i][1] = 0ull; }

    for (int st = 0; st < SCHUNK / 64; st++) {
        #pragma unroll
        for (int rr = 0; rr < 64; rr += 16) {
            const int s = rr + lr;
            const size_t gg = base + (size_t)(st * 64 + s) * EMBED + lc4;
            *(float4*)&Qs[s][lc4] = *(const float4*)(Q + gg);
            *(float4*)&Ks[s][lc4] = *(const float4*)(K + gg);
        }
        __syncthreads();

        #pragma unroll 8
        for (int ss = 0; ss < 64; ss++) {
            float4 q4 = *(const float4*)&Qs[ss][ty * 4];
            ulonglong2 k2 = *(const ulonglong2*)&Ks[ss][tx * 4];
            float qv[4] = {q4.x, q4.y, q4.z, q4.w};
            #pragma unroll
            for (int i = 0; i < 4; i++) {
                unsigned long long ad = dup2(qv[i]);
                ffma2(c2[i][0], ad, k2.x);
                ffma2(c2[i][1], ad, k2.y);
            }
        }
        __syncthreads();
    }

    float* gp = g_Gpart + ((size_t)chunk * BHEADS + bh) * DK * DK;
    #pragma unroll
    for (int i = 0; i < 4; i++) {
        const int d = ty * 4 + i;
        *(float4*)&gp[d * DK + tx * 4] =
            make_float4(lo2(c2[i][0]), hi2(c2[i][0]), lo2(c2[i][1]), hi2(c2[i][1]));
    }
}

// ---------------------------------------------------------------------------
// Kernel A: fused prep — x hi/lo split + 3x W fp16 convert, one launch.
// blocks [0, XB): x split; [XB, XB+3*WB): W converts.
// ---------------------------------------------------------------------------
#define XB  ((MTOK * EMBED) / 1024)     /* 32768 blocks */
#define WB  ((EMBED * EMBED) / 1024)    /* 1024 blocks per W */

__global__ __launch_bounds__(256)
void prep_kernel(const float* __restrict__ x,
                 const float* __restrict__ Wq, const float* __restrict__ Wk,
                 const float* __restrict__ Wv,
                 __half* __restrict__ xh, __half* __restrict__ xl,
                 __half* __restrict__ w0, __half* __restrict__ w1,
                 __half* __restrict__ w2)
{
    const int bx = blockIdx.x;
    if (bx < XB) {
        const int i = (bx * 256 + threadIdx.x) * 4;
        float4 v = *(const float4*)(x + i);
        __half h0 = __float2half_rn(v.x), h1 = __float2half_rn(v.y);
        __half h2 = __float2half_rn(v.z), h3 = __float2half_rn(v.w);
        __half l0 = __float2half_rn(v.x - __half2float(h0));
        __half l1 = __float2half_rn(v.y - __half2float(h1));
        __half l2 = __float2half_rn(v.z - __half2float(h2));
        __half l3 = __float2half_rn(v.w - __half2float(h3));
        __half2 hp0 = {h0, h1}, hp1 = {h2, h3};
        __half2 lp0 = {l0, l1}, lp1 = {l2, l3};
        *(__half2*)(xh + i)     = hp0;
        *(__half2*)(xh + i + 2) = hp1;
        *(__half2*)(xl + i)     = lp0;
        *(__half2*)(xl + i + 2) = lp1;
    } else {
        const int wi = (bx - XB) / WB;             // 0..2
        const int wb = (bx - XB) - wi * WB;
        const float* src = (wi == 0) ? Wq : (wi == 1) ? Wk : Wv;
        __half* dst = (wi == 0) ? w0 : (wi == 1) ? w1 : w2;
        const int i = (wb * 256 + threadIdx.x) * 4;
        float4 v = *(const float4*)(src + i);
        __half2 p0 = {__float2half_rn(v.x), __float2half_rn(v.y)};
        __half2 p1 = {__float2half_rn(v.z), __float2half_rn(v.w)};
        *(__half2*)(dst + i)     = p0;
        *(__half2*)(dst + i + 2) = p1;
    }
}

// ---------------------------------------------------------------------------
// Kernel B: standalone projection GEMM (used for Q and K)
// ---------------------------------------------------------------------------
__global__ __launch_bounds__(256, 2)
void gemm_split_kernel(const __half* __restrict__ Ah,
                       const __half* __restrict__ Al,
                       const __half* __restrict__ B,
                       const float* __restrict__ bias,
                       float* __restrict__ C)
{
    extern __shared__ char smem[];
    gemm_body(smem, blockIdx.x, Ah, Al, B, bias, C);
}

// ---------------------------------------------------------------------------
// Kernel C: FUSED V-projection GEMM + gram. 3072 blocks, interleaved 2:1 so
// every wave mixes tensor-pipe work (GEMM) with fma-pipe work (gram).
// ---------------------------------------------------------------------------
__global__ __launch_bounds__(256, 2)
void vgemm_gram_kernel(const __half* __restrict__ Ah,
                       const __half* __restrict__ Al,
                       const __half* __restrict__ B,
                       const float* __restrict__ bias,
                       float* __restrict__ C)
{
    extern __shared__ char smem[];
    const int bx = blockIdx.x;
    const int r = bx % 3;
    if (r < 2) {
        const int gemm_id = (bx / 3) * 2 + r;        // 0..2047
        gemm_body(smem, gemm_id, Ah, Al, B, bias, C);
    } else {
        const int gram_id = bx / 3;                  // 0..1023
        gram_body(smem, gram_id & (BHEADS - 1), gram_id >> 7);
    }
}

// ---------------------------------------------------------------------------
// Kernel D: reduce partials + softmax; write attn transposed At[e][d]
// ---------------------------------------------------------------------------
__global__ __launch_bounds__(256)
void softmax_kernel()
{
    const int gwarp = (blockIdx.x * blockDim.x + threadIdx.x) >> 5;
    const int lane = threadIdx.x & 31;
    const int bh = gwarp >> 6;
    const int d = gwarp & 63;

    float g0 = 0.f, g1 = 0.f;
    #pragma unroll
    for (int c = 0; c < NCHUNK; c++) {
        const float* gp = g_Gpart + (((size_t)c * BHEADS + bh) * DK + d) * DK;
        g0 += gp[lane];
        g1 += gp[lane + 32];
    }
    g0 *= 0.125f; g1 *= 0.125f;

    float m = fmaxf(g0, g1);
    #pragma unroll
    for (int o = 16; o > 0; o >>= 1) m = fmaxf(m, __shfl_xor_sync(0xffffffffu, m, o));
    float e0 = expf(g0 - m), e1 = expf(g1 - m);
    float s = e0 + e1;
    #pragma unroll
    for (int o = 16; o > 0; o >>= 1) s += __shfl_xor_sync(0xffffffffu, s, o);
    const float inv = 1.0f / s;

    float* at = g_At + (size_t)bh * DK * DK;
    at[lane * DK + d]        = e0 * inv;
    at[(lane + 32) * DK + d] = e1 * inv;
}

// ---------------------------------------------------------------------------
// Kernel E: output mix  out[m, h*64+d] = sum_e attn[bh][d][e] * V[m, h*64+e]
// ---------------------------------------------------------------------------
__global__ __launch_bounds__(256, 2)
void out_kernel(float* __restrict__ OUT)
{
    __shared__ float Am[64][64];
    __shared__ float Vt[64][65];

    const int m0 = blockIdx.x * 64;
    const int h  = blockIdx.y;
    const int b  = m0 >> 12;
    const int bh = b * NHEADS + h;
    const float* V = g_QKV[2];

    const int tid = threadIdx.x;
    const int tx = tid & 15, ty = tid >> 4;
    const int lr = tid >> 4, lc4 = (tid & 15) << 2;

    const float* at = g_At + (size_t)bh * DK * DK;
    #pragma unroll
    for (int rr = 0; rr < 64; rr += 16)
        *(float4*)&Am[rr + lr][lc4] = *(const float4*)&at[(rr + lr) * DK + lc4];

    #pragma unroll
    for (int rr = 0; rr < 64; rr += 16) {
        const int s = rr + lr;
        float4 v = *(const float4*)(V + (size_t)(m0 + s) * EMBED + h * DK + lc4);
        Vt[lc4 + 0][s] = v.x;
        Vt[lc4 + 1][s] = v.y;
        Vt[lc4 + 2][s] = v.z;
        Vt[lc4 + 3][s] = v.w;
    }
    __syncthreads();

    unsigned long long o2[4][2];
    #pragma unroll
    for (int i = 0; i < 4; i++) { o2[i][0] = 0ull; o2[i][1] = 0ull; }

    #pragma unroll 8
    for (int ee = 0; ee < 64; ee++) {
        ulonglong2 ap = *(const ulonglong2*)&Am[ee][tx * 4];
        #pragma unroll
        for (int si = 0; si < 4; si++) {
            unsigned long long vd = dup2(Vt[ee][ty * 4 + si]);
            ffma2(o2[si][0], vd, ap.x);
            ffma2(o2[si][1], vd, ap.y);
        }
    }

    #pragma unroll
    for (int si = 0; si < 4; si++) {
        const int m = m0 + ty * 4 + si;
        *(float4*)&OUT[(size_t)m * EMBED + h * DK + tx * 4] =
            make_float4(lo2(o2[si][0]), hi2(o2[si][0]),
                        lo2(o2[si][1]), hi2(o2[si][1]));
    }
}

// ---------------------------------------------------------------------------
// Launch
// ---------------------------------------------------------------------------
extern "C" void kernel_launch(void* const* d_in, const int* in_sizes, int n_in,
                              void* d_out, int out_size)
{
    const float* x  = (const float*)d_in[0];
    const float* Wq = (const float*)d_in[1];
    const float* bq = (const float*)d_in[2];
    const float* Wk = (const float*)d_in[3];
    const float* bk = (const float*)d_in[4];
    const float* Wv = (const float*)d_in[5];
    const float* bv = (const float*)d_in[6];
    float* out = (float*)d_out;

    cudaFuncSetAttribute(gemm_split_kernel,
                         cudaFuncAttributeMaxDynamicSharedMemorySize, G_SMEM);
    cudaFuncSetAttribute(vgemm_gram_kernel,
                         cudaFuncAttributeMaxDynamicSharedMemorySize, G_SMEM);

    __half *xh, *xl, *wb;
    cudaGetSymbolAddress((void**)&xh, g_xh);
    cudaGetSymbolAddress((void**)&xl, g_xl);
    cudaGetSymbolAddress((void**)&wb, g_w);
    float* qkv;
    cudaGetSymbolAddress((void**)&qkv, g_QKV);

    __half* w0 = wb;
    __half* w1 = wb + EMBED * EMBED;
    __half* w2 = wb + 2 * EMBED * EMBED;

    // 1) fused conversions
    prep_kernel<<<XB + 3 * WB, 256>>>(x, Wq, Wk, Wv, xh, xl, w0, w1, w2);

    // 2) Q and K projections (at the mma.sync ceiling)
    dim3 ggrid(GEMM_BLOCKS);
    gemm_split_kernel<<<ggrid, 256, G_SMEM>>>(xh, xl, w0, bq,
                                              qkv + 0ll * MTOK * EMBED);
    gemm_split_kernel<<<ggrid, 256, G_SMEM>>>(xh, xl, w1, bk,
                                              qkv + 1ll * MTOK * EMBED);

    // 3) fused: V projection (tensor pipe) + gram over Q,K (fma pipe)
    vgemm_gram_kernel<<<GEMM_BLOCKS + GRAM_BLOCKS, 256, G_SMEM>>>(
        xh, xl, w2, bv, qkv + 2ll * MTOK * EMBED);

    // 4) softmax + output mix
    softmax_kernel<<<(BHEADS * DK) / 8, 256>>>();
    out_kernel<<<dim3(MTOK / 64, NHEADS), 256>>>(out);
}